// round 12
// baseline (speedup 1.0000x reference)
#include <cuda_runtime.h>
#include <cuda_fp16.h>
#include <math.h>
#include <stdint.h>

// Problem constants
#define B 8
#define C 512
#define L 4096
#define HEADS 8
#define DHEAD 64
#define HIDDEN 512           // HEADS*DHEAD
#define QKV_CH 1536          // 3*HIDDEN
#define SQRT_C 22.627416998f // sqrt(512)
#define ATTN_SCALE 0.125f    // 64^-0.5
#define NCHUNK 8             // ctx split factor over L
#define BH (B * HEADS)

// Scratch buffers
__device__ __half g_w2h[(size_t)QKV_CH * C];        // w_qkv * g_in, fp16
__device__ __half g_wouth[(size_t)C * HIDDEN];
__device__ __half g_xhT[(size_t)B * L * C];         // (x*s)^T fp16 [b][l][c]
__device__ __half g_qkvh[(size_t)B * QKV_CH * L];   // fp16 [b][ch][l]; k rows hold exp(k)
__device__ __half g_expqT[(size_t)BH * L * DHEAD];  // exp(q) [bh][l][d]
__device__ float  g_qsum[(size_t)BH * L];           // per-(bh,l) sum of exp(q) over d
__device__ float  g_ksum[(size_t)B * HIDDEN];       // per-(b,kch) sum of exp(k) over l
__device__ float  g_ctxp[(size_t)NCHUNK * BH * DHEAD * DHEAD];
__device__ __half g_ctxh[(size_t)BH * DHEAD * DHEAD]; // ctx^T/ksum fp16 [bh][e][d]
__device__ __half g_attnT[(size_t)B * L * HIDDEN];  // fp16 [b][l][e]

// ---------------------------------------------------------------------------
// PTX helpers
// ---------------------------------------------------------------------------
__device__ __forceinline__ void cp_async16(uint32_t dst, const void* src) {
    asm volatile("cp.async.cg.shared.global [%0], [%1], 16;" :: "r"(dst), "l"(src));
}
__device__ __forceinline__ void cp_commit() {
    asm volatile("cp.async.commit_group;");
}
template <int N>
__device__ __forceinline__ void cp_wait() {
    asm volatile("cp.async.wait_group %0;" :: "n"(N));
}
__device__ __forceinline__ void ldsm_x4(uint32_t r[4], uint32_t addr) {
    asm volatile("ldmatrix.sync.aligned.m8n8.x4.shared.b16 {%0,%1,%2,%3}, [%4];"
                 : "=r"(r[0]), "=r"(r[1]), "=r"(r[2]), "=r"(r[3]) : "r"(addr));
}
__device__ __forceinline__ void mma_f16(float d[4], const uint32_t a[4],
                                        const uint32_t b[2]) {
    asm volatile(
        "mma.sync.aligned.m16n8k16.row.col.f32.f16.f16.f32 "
        "{%0,%1,%2,%3}, {%4,%5,%6,%7}, {%8,%9}, {%0,%1,%2,%3};"
        : "+f"(d[0]), "+f"(d[1]), "+f"(d[2]), "+f"(d[3])
        : "r"(a[0]), "r"(a[1]), "r"(a[2]), "r"(a[3]),
          "r"(b[0]), "r"(b[1]));
}
// fp16-accumulator form (experiment: possibly double-rate on sm_103a)
__device__ __forceinline__ void mma_f16acc(uint32_t d[2], const uint32_t a[4],
                                           const uint32_t b[2]) {
    asm volatile(
        "mma.sync.aligned.m16n8k16.row.col.f16.f16.f16.f16 "
        "{%0,%1}, {%2,%3,%4,%5}, {%6,%7}, {%0,%1};"
        : "+r"(d[0]), "+r"(d[1])
        : "r"(a[0]), "r"(a[1]), "r"(a[2]), "r"(a[3]),
          "r"(b[0]), "r"(b[1]));
}

// ---------------------------------------------------------------------------
// Weight conversions + ksum zero
// ---------------------------------------------------------------------------
__global__ void convert_wqkv_kernel(const float* __restrict__ w,
                                    const float* __restrict__ g,
                                    __half* __restrict__ w2h) {
    int i = blockIdx.x * 256 + threadIdx.x;
    w2h[i] = __float2half(w[i] * g[i & (C - 1)]);
}
__global__ void convert_wout_kernel(const float* __restrict__ w,
                                    __half* __restrict__ wh) {
    int i = blockIdx.x * 256 + threadIdx.x;
    wh[i] = __float2half(w[i]);
}
__global__ void zero_ksum_kernel(float* __restrict__ ksum) {
    ksum[blockIdx.x * 256 + threadIdx.x] = 0.f;
}

// ---------------------------------------------------------------------------
// Fused rmsnorm-scale + transpose: xhT[b][l][c] = fp16(x[b][c][l] * s[b,l])
// ---------------------------------------------------------------------------
#define NX_SMEM (512 * 33 * 4)
extern __shared__ float nx_sm[];
__global__ __launch_bounds__(256) void normxpose_kernel(const float* __restrict__ x,
                                                        __half* __restrict__ xhT) {
    float* t = nx_sm;               // t[c*33 + l]
    __shared__ float sc[32];
    int b = blockIdx.y;
    int l0 = blockIdx.x * 32;
    int tid = threadIdx.x;
    const float* xp = x + ((size_t)b * C) * L + l0;
#pragma unroll
    for (int i = 0; i < 64; i++) {
        int flat = i * 256 + tid;
        int c = flat >> 5, l = flat & 31;
        t[c * 33 + l] = xp[(size_t)c * L + l];
    }
    __syncthreads();
    int warp = tid >> 5, lane = tid & 31;
#pragma unroll
    for (int li = 0; li < 4; li++) {
        int l = warp * 4 + li;
        float ss = 0.f;
#pragma unroll
        for (int ci = 0; ci < 16; ci++) {
            float v = t[(ci * 32 + lane) * 33 + l];
            ss += v * v;
        }
#pragma unroll
        for (int off = 16; off > 0; off >>= 1)
            ss += __shfl_xor_sync(0xFFFFFFFFu, ss, off);
        if (lane == 0) sc[l] = SQRT_C / fmaxf(sqrtf(ss), 1e-12f);
    }
    __syncthreads();
    __half* op = xhT + ((size_t)b * L + l0) * C;
#pragma unroll
    for (int i = 0; i < 64; i++) {
        int flat = i * 256 + tid;
        int l = flat >> 9, c = flat & 511;
        op[(size_t)l * C + c] = __float2half(t[c * 33 + l] * sc[l]);
    }
}

// ---------------------------------------------------------------------------
// QKV GEMM: 128x128x32, 8 warps (2x4) of 64x32, 3-stage cp.async.
// fp16 accumulators, flushed to fp32 every 2 k-tiles (K=64 window).
// Region-specialized epilogue (q -> exp -> expqT + qsum;
// k -> exp in place + ksum atomics; v -> plain).
// ---------------------------------------------------------------------------
#define H_LD 40
#define H_TILEB (128 * H_LD * 2)
#define STAGES 3
#define GEMM_SMEM (STAGES * 2 * H_TILEB)

extern __shared__ __half sgm_h[];

__device__ __forceinline__ void qkv_load_tile(uint32_t sa, uint32_t sb, int stage,
                                              const __half* Ap, const __half* Bp,
                                              int k0, int K, int tid) {
#pragma unroll
    for (int i = 0; i < 2; i++) {
        int c = tid + i * 256;
        int row = c >> 2, kc = (c & 3) * 8;
        cp_async16(sa + stage * H_TILEB + (row * H_LD + kc) * 2,
                   Ap + (size_t)row * K + k0 + kc);
    }
#pragma unroll
    for (int i = 0; i < 2; i++) {
        int c = tid + i * 256;
        int row = c >> 2, kc = (c & 3) * 8;
        cp_async16(sb + stage * H_TILEB + (row * H_LD + kc) * 2,
                   Bp + (size_t)row * K + k0 + kc);
    }
}

__global__ __launch_bounds__(256) void gemm_qkv(
    const __half* __restrict__ A, const __half* __restrict__ Bb,
    __half* __restrict__ Cb, __half* __restrict__ expqT,
    float* __restrict__ qsum, float* __restrict__ ksum,
    int K, int ldc, size_t strideB, size_t strideC) {
    uint32_t sa = (uint32_t)__cvta_generic_to_shared(sgm_h);
    uint32_t sb = sa + STAGES * H_TILEB;

    const int tid = threadIdx.x;
    const int lane = tid & 31;
    const int warp = tid >> 5;
    const int gid = lane >> 2;
    const int t4 = lane & 3;
    const int wm = warp >> 2;
    const int wn = warp & 3;
    const int t8 = lane >> 3;
    const int r8 = lane & 7;

    const __half* Ap = A + (size_t)blockIdx.y * 128 * K;
    const __half* Bp = Bb + (size_t)blockIdx.z * strideB + (size_t)blockIdx.x * 128 * K;
    __half* Cp = Cb + (size_t)blockIdx.z * strideC +
                 (size_t)blockIdx.y * 128 * ldc + (size_t)blockIdx.x * 128;

    float acc[4][4][4];
    uint32_t hacc[4][4][2];
#pragma unroll
    for (int mi = 0; mi < 4; mi++)
#pragma unroll
        for (int ni = 0; ni < 4; ni++) {
#pragma unroll
            for (int r = 0; r < 4; r++) acc[mi][ni][r] = 0.f;
            hacc[mi][ni][0] = 0u;
            hacc[mi][ni][1] = 0u;
        }

    const int ktiles = K >> 5;
#pragma unroll
    for (int s = 0; s < STAGES - 1; s++) {
        qkv_load_tile(sa, sb, s, Ap, Bp, s * 32, K, tid);
        cp_commit();
    }
    cp_wait<STAGES - 2>();
    __syncthreads();

    for (int kt = 0; kt < ktiles; kt++) {
        uint32_t abase = sa + (kt % STAGES) * H_TILEB;
        uint32_t bbase = sb + (kt % STAGES) * H_TILEB;
#pragma unroll
        for (int kk = 0; kk < 2; kk++) {
            const int kbh = kk * 16;
            uint32_t af[4][4], bf[4][2];
#pragma unroll
            for (int mi = 0; mi < 4; mi++) {
                int row = wm * 64 + mi * 16 + r8 + (t8 & 1) * 8;
                int col = kbh + (t8 >> 1) * 8;
                ldsm_x4(af[mi], abase + (row * H_LD + col) * 2);
            }
#pragma unroll
            for (int np = 0; np < 2; np++) {
                int row = wn * 32 + np * 16 + r8 + (t8 >> 1) * 8;
                int col = kbh + (t8 & 1) * 8;
                uint32_t r4[4];
                ldsm_x4(r4, bbase + (row * H_LD + col) * 2);
                bf[np * 2][0] = r4[0]; bf[np * 2][1] = r4[1];
                bf[np * 2 + 1][0] = r4[2]; bf[np * 2 + 1][1] = r4[3];
            }
#pragma unroll
            for (int mi = 0; mi < 4; mi++)
#pragma unroll
                for (int ni = 0; ni < 4; ni++)
                    mma_f16acc(hacc[mi][ni], af[mi], bf[ni]);
        }
        // flush fp16 accumulators to fp32 every 2 k-tiles
        if ((kt & 1) == 1) {
#pragma unroll
            for (int mi = 0; mi < 4; mi++)
#pragma unroll
                for (int ni = 0; ni < 4; ni++) {
                    float2 lo = __half22float2(*(__half2*)&hacc[mi][ni][0]);
                    float2 hi = __half22float2(*(__half2*)&hacc[mi][ni][1]);
                    acc[mi][ni][0] += lo.x;
                    acc[mi][ni][1] += lo.y;
                    acc[mi][ni][2] += hi.x;
                    acc[mi][ni][3] += hi.y;
                    hacc[mi][ni][0] = 0u;
                    hacc[mi][ni][1] = 0u;
                }
        }
        int nt = kt + STAGES - 1;
        if (nt < ktiles) {
            qkv_load_tile(sa, sb, nt % STAGES, Ap, Bp, nt * 32, K, tid);
            cp_commit();
            cp_wait<STAGES - 2>();
        } else {
            cp_wait<0>();
        }
        __syncthreads();
    }

    const int b = blockIdx.z;
    const int l0 = blockIdx.x * 128;
    const int region = blockIdx.y >> 2;

    if (region == 0) {
        // --- q: exp -> expqT[bh][l][d], per-(h,l) sums -> qsum ---
        const int h = (blockIdx.y << 1) + wm;
        __half* qtb = expqT + (((size_t)b * HEADS + h) * L + l0) * DHEAD;
        float cs0[4] = {0.f, 0.f, 0.f, 0.f};
        float cs1[4] = {0.f, 0.f, 0.f, 0.f};
#pragma unroll
        for (int mi = 0; mi < 4; mi++) {
            const int d0 = mi * 16 + gid;
#pragma unroll
            for (int ni = 0; ni < 4; ni++) {
                const int col = wn * 32 + ni * 8 + t4 * 2;
                float e0 = expf(acc[mi][ni][0]);
                float e1 = expf(acc[mi][ni][1]);
                float e2 = expf(acc[mi][ni][2]);
                float e3 = expf(acc[mi][ni][3]);
                __half* q0 = qtb + (size_t)col * DHEAD;
                __half* q1 = q0 + DHEAD;
                q0[d0] = __float2half(e0);
                q0[d0 + 8] = __float2half(e2);
                q1[d0] = __float2half(e1);
                q1[d0 + 8] = __float2half(e3);
                cs0[ni] += e0 + e2;
                cs1[ni] += e1 + e3;
            }
        }
#pragma unroll
        for (int ni = 0; ni < 4; ni++) {
            cs0[ni] += __shfl_xor_sync(0xFFFFFFFFu, cs0[ni], 4);
            cs0[ni] += __shfl_xor_sync(0xFFFFFFFFu, cs0[ni], 8);
            cs0[ni] += __shfl_xor_sync(0xFFFFFFFFu, cs0[ni], 16);
            cs1[ni] += __shfl_xor_sync(0xFFFFFFFFu, cs1[ni], 4);
            cs1[ni] += __shfl_xor_sync(0xFFFFFFFFu, cs1[ni], 8);
            cs1[ni] += __shfl_xor_sync(0xFFFFFFFFu, cs1[ni], 16);
            if (gid == 0) {
                const int col = wn * 32 + ni * 8 + t4 * 2;
                float* qs = qsum + ((size_t)b * HEADS + h) * L + l0 + col;
                qs[0] = cs0[ni];
                qs[1] = cs1[ni];
            }
        }
    } else if (region == 1) {
        // --- k: exp in place + per-row sums (atomic) ---
#pragma unroll
        for (int mi = 0; mi < 4; mi++) {
            const int r0 = wm * 64 + mi * 16 + gid;
            float rs0 = 0.f, rs1 = 0.f;
#pragma unroll
            for (int ni = 0; ni < 4; ni++) {
                const int col = wn * 32 + ni * 8 + t4 * 2;
                float e0 = expf(acc[mi][ni][0]);
                float e1 = expf(acc[mi][ni][1]);
                float e2 = expf(acc[mi][ni][2]);
                float e3 = expf(acc[mi][ni][3]);
                *(__half2*)&Cp[(size_t)r0 * ldc + col] = __floats2half2_rn(e0, e1);
                *(__half2*)&Cp[(size_t)(r0 + 8) * ldc + col] = __floats2half2_rn(e2, e3);
                rs0 += e0 + e1;
                rs1 += e2 + e3;
            }
            rs0 += __shfl_xor_sync(0xFFFFFFFFu, rs0, 1);
            rs0 += __shfl_xor_sync(0xFFFFFFFFu, rs0, 2);
            rs1 += __shfl_xor_sync(0xFFFFFFFFu, rs1, 1);
            rs1 += __shfl_xor_sync(0xFFFFFFFFu, rs1, 2);
            if (t4 == 0) {
                const int ch = (blockIdx.y - 4) * 128 + r0;
                atomicAdd(&ksum[(size_t)b * HIDDEN + ch], rs0);
                atomicAdd(&ksum[(size_t)b * HIDDEN + ch + 8], rs1);
            }
        }
    } else {
        // --- v: plain fp16 store ---
#pragma unroll
        for (int mi = 0; mi < 4; mi++) {
            const int r0 = wm * 64 + mi * 16 + gid;
#pragma unroll
            for (int ni = 0; ni < 4; ni++) {
                const int col = wn * 32 + ni * 8 + t4 * 2;
                *(__half2*)&Cp[(size_t)r0 * ldc + col] =
                    __floats2half2_rn(acc[mi][ni][0], acc[mi][ni][1]);
                *(__half2*)&Cp[(size_t)(r0 + 8) * ldc + col] =
                    __floats2half2_rn(acc[mi][ni][2], acc[mi][ni][3]);
            }
        }
    }
}

// ---------------------------------------------------------------------------
// ctx partial via HMMA (fp32 accum — positive exp(k) sums, keep exact):
// ctxp[chunk][bh] = expk[64, 512chunk] @ v[64, 512chunk]^T
// ---------------------------------------------------------------------------
#define CTX_LD 40
#define CTX_TILEB (64 * CTX_LD * 2)

__global__ __launch_bounds__(128) void ctx_part_mma(const __half* __restrict__ qkvh,
                                                    float* __restrict__ ctxp) {
    __shared__ __half csk[3 * 64 * CTX_LD];
    __shared__ __half csv[3 * 64 * CTX_LD];
    uint32_t ska = (uint32_t)__cvta_generic_to_shared(csk);
    uint32_t skv = (uint32_t)__cvta_generic_to_shared(csv);

    int bh = blockIdx.x;
    int chunk = blockIdx.y;
    int b = bh >> 3, h = bh & 7;
    const __half* kp = qkvh + ((size_t)b * QKV_CH + HIDDEN + h * DHEAD) * L;
    const __half* vp = qkvh + ((size_t)b * QKV_CH + 2 * HIDDEN + h * DHEAD) * L;
    const int lbeg = chunk * (L / NCHUNK);

    const int tid = threadIdx.x;
    const int lane = tid & 31;
    const int warp = tid >> 5;
    const int gid = lane >> 2;
    const int t4 = lane & 3;
    const int t8 = lane >> 3;
    const int r8 = lane & 7;

    auto load_stage = [&](int stage, int kt) {
        int l0 = lbeg + kt * 32;
#pragma unroll
        for (int i = 0; i < 2; i++) {
            int flat = i * 128 + tid;
            int row = flat >> 2, kc = (flat & 3) * 8;
            cp_async16(ska + stage * CTX_TILEB + (row * CTX_LD + kc) * 2,
                       kp + (size_t)row * L + l0 + kc);
            cp_async16(skv + stage * CTX_TILEB + (row * CTX_LD + kc) * 2,
                       vp + (size_t)row * L + l0 + kc);
        }
    };

    float acc[8][4];
#pragma unroll
    for (int ni = 0; ni < 8; ni++)
#pragma unroll
        for (int r = 0; r < 4; r++) acc[ni][r] = 0.f;

    const int ktiles = (L / NCHUNK) >> 5;
#pragma unroll
    for (int s = 0; s < 2; s++) {
        load_stage(s, s);
        cp_commit();
    }
    cp_wait<1>();
    __syncthreads();

    for (int kt = 0; kt < ktiles; kt++) {
        uint32_t abase = ska + (kt % 3) * CTX_TILEB;
        uint32_t bbase = skv + (kt % 3) * CTX_TILEB;
#pragma unroll
        for (int kk = 0; kk < 2; kk++) {
            const int kbh = kk * 16;
            uint32_t af[4], bf[8][2];
            {
                int row = warp * 16 + r8 + (t8 & 1) * 8;
                int col = kbh + (t8 >> 1) * 8;
                ldsm_x4(af, abase + (row * CTX_LD + col) * 2);
            }
#pragma unroll
            for (int np = 0; np < 4; np++) {
                int row = np * 16 + r8 + (t8 >> 1) * 8;
                int col = kbh + (t8 & 1) * 8;
                uint32_t r4[4];
                ldsm_x4(r4, bbase + (row * CTX_LD + col) * 2);
                bf[np * 2][0] = r4[0]; bf[np * 2][1] = r4[1];
                bf[np * 2 + 1][0] = r4[2]; bf[np * 2 + 1][1] = r4[3];
            }
#pragma unroll
            for (int ni = 0; ni < 8; ni++)
                mma_f16(acc[ni], af, bf[ni]);
        }
        int nt = kt + 2;
        if (nt < ktiles) {
            load_stage(nt % 3, nt);
            cp_commit();
            cp_wait<1>();
        } else {
            cp_wait<0>();
        }
        __syncthreads();
    }

    float* cp = ctxp + ((size_t)chunk * BH + bh) * (DHEAD * DHEAD);
    int d = warp * 16 + gid;
#pragma unroll
    for (int ni = 0; ni < 8; ni++) {
        int col = ni * 8 + t4 * 2;
        *(float2*)&cp[d * DHEAD + col] = make_float2(acc[ni][0], acc[ni][1]);
        *(float2*)&cp[(d + 8) * DHEAD + col] = make_float2(acc[ni][2], acc[ni][3]);
    }
}

// ---------------------------------------------------------------------------
// Reduce chunks + divide by ksum, emit ctxh fp16 transposed [bh][e][d]
// ---------------------------------------------------------------------------
__global__ void ctx_reduce_kernel(const float* __restrict__ ctxp,
                                  const float* __restrict__ ksum,
                                  __half* __restrict__ ctxh) {
    int i = blockIdx.x * 256 + threadIdx.x; // over BH*4096
    int bh = i >> 12;
    int rem = i & 4095;
    int d = rem >> 6, e = rem & 63;
    float s = 0.f;
#pragma unroll
    for (int c = 0; c < NCHUNK; c++)
        s += ctxp[(size_t)c * (BH * DHEAD * DHEAD) + i];
    int b = bh >> 3, h = bh & 7;
    float kv = ksum[(size_t)b * HIDDEN + h * DHEAD + d];
    ctxh[((size_t)bh << 12) + e * DHEAD + d] = __float2half(s / kv);
}

// ---------------------------------------------------------------------------
// attn via HMMA: attnT[l][h*64+e] = (scale/qsum[l]) * sum_d expq[l][d]*ctxh[e][d]
// ---------------------------------------------------------------------------
#define AQ_LD 72
__global__ __launch_bounds__(128) void attn_mma(const __half* __restrict__ expqT,
                                                const float* __restrict__ qsum,
                                                const __half* __restrict__ ctxh,
                                                __half* __restrict__ attnT) {
    __shared__ __half As[128 * AQ_LD];
    __shared__ __half Bs[64 * AQ_LD];
    uint32_t sa = (uint32_t)__cvta_generic_to_shared(As);
    uint32_t sb = (uint32_t)__cvta_generic_to_shared(Bs);

    const int l0 = blockIdx.x * 128;
    const int bh = blockIdx.y;
    const int b = bh >> 3, h = bh & 7;

    const int tid = threadIdx.x;
    const int lane = tid & 31;
    const int warp = tid >> 5;
    const int gid = lane >> 2;
    const int t4 = lane & 3;
    const int t8 = lane >> 3;
    const int r8 = lane & 7;
    const int wm = warp >> 1;
    const int wn = warp & 1;

    const __half* qp = expqT + ((size_t)bh * L + l0) * DHEAD;
    const __half* cp = ctxh + ((size_t)bh << 12);

#pragma unroll
    for (int i = 0; i < 8; i++) {
        int flat = i * 128 + tid;
        int row = flat >> 3, seg = flat & 7;
        cp_async16(sa + (row * AQ_LD + seg * 8) * 2, qp + (size_t)row * DHEAD + seg * 8);
    }
#pragma unroll
    for (int i = 0; i < 4; i++) {
        int flat = i * 128 + tid;
        int row = flat >> 3, seg = flat & 7;
        cp_async16(sb + (row * AQ_LD + seg * 8) * 2, cp + (size_t)row * DHEAD + seg * 8);
    }
    cp_commit();
    cp_wait<0>();
    __syncthreads();

    float acc[4][4][4];
#pragma unroll
    for (int mi = 0; mi < 4; mi++)
#pragma unroll
        for (int ni = 0; ni < 4; ni++)
#pragma unroll
            for (int r = 0; r < 4; r++) acc[mi][ni][r] = 0.f;

#pragma unroll
    for (int kt = 0; kt < 4; kt++) {
        const int kbh = kt * 16;
        uint32_t af[4][4], bf[4][2];
#pragma unroll
        for (int mi = 0; mi < 4; mi++) {
            int row = wm * 64 + mi * 16 + r8 + (t8 & 1) * 8;
            int col = kbh + (t8 >> 1) * 8;
            ldsm_x4(af[mi], sa + (row * AQ_LD + col) * 2);
        }
#pragma unroll
        for (int np = 0; np < 2; np++) {
            int row = wn * 32 + np * 16 + r8 + (t8 >> 1) * 8;
            int col = kbh + (t8 & 1) * 8;
            uint32_t r4[4];
            ldsm_x4(r4, sb + (row * AQ_LD + col) * 2);
            bf[np * 2][0] = r4[0]; bf[np * 2][1] = r4[1];
            bf[np * 2 + 1][0] = r4[2]; bf[np * 2 + 1][1] = r4[3];
        }
#pragma unroll
        for (int mi = 0; mi < 4; mi++)
#pragma unroll
            for (int ni = 0; ni < 4; ni++)
                mma_f16(acc[mi][ni], af[mi], bf[ni]);
    }

    const float* qs = qsum + (size_t)bh * L + l0;
#pragma unroll
    for (int mi = 0; mi < 4; mi++) {
        const int r0 = wm * 64 + mi * 16 + gid;
        const float inv0 = ATTN_SCALE / qs[r0];
        const float inv1 = ATTN_SCALE / qs[r0 + 8];
        __half* o0 = attnT + ((size_t)b * L + l0 + r0) * HIDDEN + h * DHEAD;
        __half* o1 = attnT + ((size_t)b * L + l0 + r0 + 8) * HIDDEN + h * DHEAD;
#pragma unroll
        for (int ni = 0; ni < 4; ni++) {
            const int col = wn * 32 + ni * 8 + t4 * 2;
            *(__half2*)&o0[col] = __floats2half2_rn(acc[mi][ni][0] * inv0,
                                                    acc[mi][ni][1] * inv0);
            *(__half2*)&o1[col] = __floats2half2_rn(acc[mi][ni][2] * inv1,
                                                    acc[mi][ni][3] * inv1);
        }
    }
}

// ---------------------------------------------------------------------------
// Fused out-GEMM + bias + channel RMSNorm + residual.
// ---------------------------------------------------------------------------
#define OA_BYTES (512 * H_LD * 2)
#define OB_BYTES (64 * H_LD * 2)
#define OSTG_BYTES (OA_BYTES + OB_BYTES)
#define OSTAGES 3
#define XS_OFF (OSTAGES * OSTG_BYTES)
#define XS_LDF 68
#define OUT_SMEM (XS_OFF + 256 * XS_LDF * 4)

__global__ __launch_bounds__(512) void gemm_out_fused(
    const __half* __restrict__ A, const __half* __restrict__ Bb,
    const float* __restrict__ bias, const float* __restrict__ gout,
    const float* __restrict__ x, float* __restrict__ out) {
    __shared__ float colsum[64];
    uint32_t sbase = (uint32_t)__cvta_generic_to_shared(sgm_h);
    float* xs = (float*)((char*)sgm_h + XS_OFF);

    const int tid = threadIdx.x;
    const int lane = tid & 31;
    const int warp = tid >> 5;
    const int gid = lane >> 2;
    const int t4 = lane & 3;
    const int t8 = lane >> 3;
    const int r8 = lane & 7;
    const int bz = blockIdx.y;
    const int l0 = blockIdx.x * 64;

    const __half* Bp = Bb + ((size_t)bz * L + l0) * HIDDEN;

    float acc[2][8][4];
#pragma unroll
    for (int mi = 0; mi < 2; mi++)
#pragma unroll
        for (int ni = 0; ni < 8; ni++)
#pragma unroll
            for (int r = 0; r < 4; r++) acc[mi][ni][r] = 0.f;

    auto load_stage = [&](int kt) {
        uint32_t sA = sbase + (kt % OSTAGES) * OSTG_BYTES;
        uint32_t sB = sA + OA_BYTES;
        int k0 = kt * 32;
#pragma unroll
        for (int i = 0; i < 4; i++) {
            int c = tid + i * 512;
            int row = c >> 2, kc = (c & 3) * 8;
            cp_async16(sA + (row * H_LD + kc) * 2, A + (size_t)row * HIDDEN + k0 + kc);
        }
        if (tid < 256) {
            int row = tid >> 2, kc = (tid & 3) * 8;
            cp_async16(sB + (row * H_LD + kc) * 2, Bp + (size_t)row * HIDDEN + k0 + kc);
        }
    };
    auto load_xchunk = [&](int c) {
        if (tid < 256) {
            int flat = c * 256 + tid;
            int row = flat >> 4, seg = flat & 15;
            cp_async16(sbase + XS_OFF + row * (XS_LDF * 4) + seg * 16,
                       x + ((size_t)bz * C + row) * L + l0 + seg * 4);
        }
    };

    const int ktiles = HIDDEN >> 5;
#pragma unroll
    for (int s = 0; s < OSTAGES - 1; s++) {
        load_stage(s);
        load_xchunk(s);
        cp_commit();
    }
    cp_wait<OSTAGES - 2>();
    __syncthreads();

    for (int kt = 0; kt < ktiles; kt++) {
        uint32_t abase = sbase + (kt % OSTAGES) * OSTG_BYTES;
        uint32_t bbase = abase + OA_BYTES;
#pragma unroll
        for (int kk = 0; kk < 2; kk++) {
            const int kbh = kk * 16;
            uint32_t af[2][4], bf[8][2];
#pragma unroll
            for (int mi = 0; mi < 2; mi++) {
                int row = warp * 32 + mi * 16 + r8 + (t8 & 1) * 8;
                int col = kbh + (t8 >> 1) * 8;
                ldsm_x4(af[mi], abase + (row * H_LD + col) * 2);
            }
#pragma unroll
            for (int np = 0; np < 4; np++) {
                int row = np * 16 + r8 + (t8 >> 1) * 8;
                int col = kbh + (t8 & 1) * 8;
                uint32_t r4[4];
                ldsm_x4(r4, bbase + (row * H_LD + col) * 2);
                bf[np * 2][0] = r4[0]; bf[np * 2][1] = r4[1];
                bf[np * 2 + 1][0] = r4[2]; bf[np * 2 + 1][1] = r4[3];
            }
#pragma unroll
            for (int mi = 0; mi < 2; mi++)
#pragma unroll
                for (int ni = 0; ni < 8; ni++)
                    mma_f16(acc[mi][ni], af[mi], bf[ni]);
        }
        int nt = kt + OSTAGES - 1;
        if (nt < ktiles) {
            load_stage(nt);
            load_xchunk(nt);
            cp_commit();
            cp_wait<OSTAGES - 2>();
        } else {
            cp_wait<0>();
        }
        __syncthreads();
    }

    float bvs[2][2];
#pragma unroll
    for (int mi = 0; mi < 2; mi++) {
        int r0 = warp * 32 + mi * 16 + gid;
        bvs[mi][0] = bias[r0];
        bvs[mi][1] = bias[r0 + 8];
    }
    if (tid < 64) colsum[tid] = 0.f;
    __syncthreads();

#pragma unroll
    for (int ni = 0; ni < 8; ni++) {
#pragma unroll
        for (int c01 = 0; c01 < 2; c01++) {
            float part = 0.f;
#pragma unroll
            for (int mi = 0; mi < 2; mi++) {
                float v0 = acc[mi][ni][c01] + bvs[mi][0];
                float v1 = acc[mi][ni][2 + c01] + bvs[mi][1];
                acc[mi][ni][c01] = v0;
                acc[mi][ni][2 + c01] = v1;
                part += v0 * v0 + v1 * v1;
            }
            part += __shfl_xor_sync(0xFFFFFFFFu, part, 4);
            part += __shfl_xor_sync(0xFFFFFFFFu, part, 8);
            part += __shfl_xor_sync(0xFFFFFFFFu, part, 16);
            if (gid == 0) atomicAdd(&colsum[ni * 8 + t4 * 2 + c01], part);
        }
    }
    __syncthreads();

    float scl[8][2];
#pragma unroll
    for (int ni = 0; ni < 8; ni++) {
        int col = ni * 8 + t4 * 2;
        scl[ni][0] = SQRT_C / fmaxf(sqrtf(colsum[col]), 1e-12f);
        scl[ni][1] = SQRT_C / fmaxf(sqrtf(colsum[col + 1]), 1e-12f);
    }

#pragma unroll
    for (int mi = 0; mi < 2; mi++) {
        int r0 = warp * 32 + mi * 16 + gid;
        float g0 = gout[r0], g1 = gout[r0 + 8];
        const float* xr0;
        const float* xr1;
        if (r0 + 8 < 256) {
            xr0 = xs + r0 * XS_LDF;
            xr1 = xs + (r0 + 8) * XS_LDF;
        } else {
            xr0 = x + ((size_t)bz * C + r0) * L + l0;
            xr1 = x + ((size_t)bz * C + r0 + 8) * L + l0;
        }
        float* or0 = out + ((size_t)bz * C + r0) * L + l0;
        float* or1 = out + ((size_t)bz * C + r0 + 8) * L + l0;
#pragma unroll
        for (int ni = 0; ni < 8; ni++) {
            int col = ni * 8 + t4 * 2;
            float2 xv0 = *(const float2*)&xr0[col];
            float2 xv1 = *(const float2*)&xr1[col];
            float2 v0 = make_float2(acc[mi][ni][0] * scl[ni][0] * g0 + xv0.x,
                                    acc[mi][ni][1] * scl[ni][1] * g0 + xv0.y);
            float2 v1 = make_float2(acc[mi][ni][2] * scl[ni][0] * g1 + xv1.x,
                                    acc[mi][ni][3] * scl[ni][1] * g1 + xv1.y);
            *(float2*)&or0[col] = v0;
            *(float2*)&or1[col] = v1;
        }
    }
}

// ---------------------------------------------------------------------------
extern "C" void kernel_launch(void* const* d_in, const int* in_sizes, int n_in,
                              void* d_out, int out_size) {
    const float* x     = (const float*)d_in[0];
    const float* g_in  = (const float*)d_in[1];
    const float* w_qkv = (const float*)d_in[2];
    const float* w_out = (const float*)d_in[3];
    const float* b_out = (const float*)d_in[4];
    const float* g_out = (const float*)d_in[5];
    float* out = (float*)d_out;

    __half *w2h, *wouth, *xhT, *qkvh, *expqT, *ctxh, *attnT;
    float *qsum, *ksum, *ctxp;
    cudaGetSymbolAddress((void**)&w2h, g_w2h);
    cudaGetSymbolAddress((void**)&wouth, g_wouth);
    cudaGetSymbolAddress((void**)&xhT, g_xhT);
    cudaGetSymbolAddress((void**)&qkvh, g_qkvh);
    cudaGetSymbolAddress((void**)&expqT, g_expqT);
    cudaGetSymbolAddress((void**)&qsum, g_qsum);
    cudaGetSymbolAddress((void**)&ksum, g_ksum);
    cudaGetSymbolAddress((void**)&ctxp, g_ctxp);
    cudaGetSymbolAddress((void**)&ctxh, g_ctxh);
    cudaGetSymbolAddress((void**)&attnT, g_attnT);

    cudaFuncSetAttribute(normxpose_kernel, cudaFuncAttributeMaxDynamicSharedMemorySize,
                         NX_SMEM);
    cudaFuncSetAttribute(gemm_qkv, cudaFuncAttributeMaxDynamicSharedMemorySize,
                         GEMM_SMEM);
    cudaFuncSetAttribute(gemm_out_fused, cudaFuncAttributeMaxDynamicSharedMemorySize,
                         OUT_SMEM);

    // 0. weight conversions + ksum zero
    convert_wqkv_kernel<<<(QKV_CH * C) / 256, 256>>>(w_qkv, g_in, w2h);
    convert_wout_kernel<<<(C * HIDDEN) / 256, 256>>>(w_out, wouth);
    zero_ksum_kernel<<<(B * HIDDEN) / 256, 256>>>(ksum);

    // 1. fused rmsnorm scale + transpose -> xhT fp16
    normxpose_kernel<<<dim3(L / 32, B), 256, NX_SMEM>>>(x, xhT);

    // 2. qkv GEMM (fp16-accum experiment) with fused exp epilogues
    gemm_qkv<<<dim3(L / 128, QKV_CH / 128, B), 256, GEMM_SMEM>>>(
        w2h, xhT, qkvh, expqT, qsum, ksum, C, L,
        (size_t)L * C, (size_t)QKV_CH * L);

    // 3. context partials via HMMA (fp32 accum), reduce + /ksum -> ctxh
    ctx_part_mma<<<dim3(BH, NCHUNK), 128>>>(qkvh, ctxp);
    ctx_reduce_kernel<<<(BH * DHEAD * DHEAD) / 256, 256>>>(ctxp, ksum, ctxh);

    // 4. attn via HMMA -> attnT
    attn_mma<<<dim3(L / 128, BH), 128>>>(expqT, qsum, ctxh, attnT);

    // 5. out = rmsnorm(wouth @ attn + b_out)*g_out + x
    gemm_out_fused<<<dim3(L / 64, B), 512, OUT_SMEM>>>(
        wouth, attnT, b_out, g_out, x, out);
}

// round 13
// speedup vs baseline: 1.2803x; 1.2803x over previous
#include <cuda_runtime.h>
#include <cuda_fp16.h>
#include <math.h>
#include <stdint.h>

// Problem constants
#define B 8
#define C 512
#define L 4096
#define HEADS 8
#define DHEAD 64
#define HIDDEN 512           // HEADS*DHEAD
#define QKV_CH 1536          // 3*HIDDEN
#define SQRT_C 22.627416998f // sqrt(512)
#define ATTN_SCALE 0.125f    // 64^-0.5
#define NCHUNK 8             // ctx split factor over L
#define BH (B * HEADS)

// Scratch buffers
__device__ __half g_w2h[(size_t)QKV_CH * C];        // w_qkv * g_in, fp16
__device__ __half g_wouth[(size_t)C * HIDDEN];
__device__ __half g_xhT[(size_t)B * L * C];         // (x*s)^T fp16 [b][l][c]
__device__ __half g_qkvh[(size_t)B * QKV_CH * L];   // fp16 [b][ch][l]; k rows hold exp(k)
__device__ __half g_expqT[(size_t)BH * L * DHEAD];  // exp(q) [bh][l][d]
__device__ float  g_qsum[(size_t)BH * L];           // per-(bh,l) sum of exp(q) over d
__device__ float  g_ksum[(size_t)B * HIDDEN];       // per-(b,kch) sum of exp(k) over l
__device__ float  g_ctxp[(size_t)NCHUNK * BH * DHEAD * DHEAD];
__device__ __half g_ctxh[(size_t)BH * DHEAD * DHEAD]; // ctx^T/ksum fp16 [bh][e][d]
__device__ __half g_attnT[(size_t)B * L * HIDDEN];  // fp16 [b][l][e]

// ---------------------------------------------------------------------------
// PTX helpers
// ---------------------------------------------------------------------------
__device__ __forceinline__ void cp_async16(uint32_t dst, const void* src) {
    asm volatile("cp.async.cg.shared.global [%0], [%1], 16;" :: "r"(dst), "l"(src));
}
__device__ __forceinline__ void cp_commit() {
    asm volatile("cp.async.commit_group;");
}
template <int N>
__device__ __forceinline__ void cp_wait() {
    asm volatile("cp.async.wait_group %0;" :: "n"(N));
}
__device__ __forceinline__ void ldsm_x4(uint32_t r[4], uint32_t addr) {
    asm volatile("ldmatrix.sync.aligned.m8n8.x4.shared.b16 {%0,%1,%2,%3}, [%4];"
                 : "=r"(r[0]), "=r"(r[1]), "=r"(r[2]), "=r"(r[3]) : "r"(addr));
}
__device__ __forceinline__ void mma_f16(float d[4], const uint32_t a[4],
                                        const uint32_t b[2]) {
    asm volatile(
        "mma.sync.aligned.m16n8k16.row.col.f32.f16.f16.f32 "
        "{%0,%1,%2,%3}, {%4,%5,%6,%7}, {%8,%9}, {%0,%1,%2,%3};"
        : "+f"(d[0]), "+f"(d[1]), "+f"(d[2]), "+f"(d[3])
        : "r"(a[0]), "r"(a[1]), "r"(a[2]), "r"(a[3]),
          "r"(b[0]), "r"(b[1]));
}

// ---------------------------------------------------------------------------
// Merged prologue: w2h, wouth conversions + ksum zero (one launch)
// grid = QKV_CH*C/256 = 3072
// ---------------------------------------------------------------------------
__global__ void prologue_kernel(const float* __restrict__ w_qkv,
                                const float* __restrict__ g_in,
                                const float* __restrict__ w_out,
                                __half* __restrict__ w2h,
                                __half* __restrict__ wouth,
                                float* __restrict__ ksum) {
    int i = blockIdx.x * 256 + threadIdx.x;
    w2h[i] = __float2half(w_qkv[i] * g_in[i & (C - 1)]);
    if (i < C * HIDDEN) wouth[i] = __float2half(w_out[i]);
    if (i < B * HIDDEN) ksum[i] = 0.f;
}

// ---------------------------------------------------------------------------
// Fused rmsnorm-scale + transpose: xhT[b][l][c] = fp16(x[b][c][l] * s[b,l])
// fp16 staging (34 KB smem -> higher occupancy); ss computed online at load.
// ---------------------------------------------------------------------------
#define NXS 34
__global__ __launch_bounds__(256) void normxpose_kernel(const float* __restrict__ x,
                                                        __half* __restrict__ xhT) {
    __shared__ __half t[512 * NXS];   // t[c*NXS + l]
    __shared__ float ssred[8][32];
    __shared__ float sc[32];
    int b = blockIdx.y;
    int l0 = blockIdx.x * 32;
    int tid = threadIdx.x;
    int l = tid & 31;                  // fixed per thread in load loop
    const float* xp = x + ((size_t)b * C) * L + l0;
    float ss = 0.f;
#pragma unroll
    for (int i = 0; i < 64; i++) {
        int c = i * 8 + (tid >> 5);
        float v = xp[(size_t)c * L + l];
        ss += v * v;
        t[c * NXS + l] = __float2half(v);
    }
    ssred[tid >> 5][l] = ss;
    __syncthreads();
    if (tid < 32) {
        float s = 0.f;
#pragma unroll
        for (int j = 0; j < 8; j++) s += ssred[j][tid];
        sc[tid] = SQRT_C / fmaxf(sqrtf(s), 1e-12f);
    }
    __syncthreads();
    __half* op = xhT + ((size_t)b * L + l0) * C;
#pragma unroll
    for (int i = 0; i < 64; i++) {
        int flat = i * 256 + tid;
        int lo = flat >> 9, c = flat & 511;
        op[(size_t)lo * C + c] =
            __float2half(__half2float(t[c * NXS + lo]) * sc[lo]);
    }
}

// ---------------------------------------------------------------------------
// QKV GEMM: 128x128x32, 8 warps (2x4) of 64x32, 3-stage cp.async, fp32 accum.
// Region-specialized epilogue (q -> exp -> expqT + qsum;
// k -> exp in place + ksum atomics; v -> plain).
// ---------------------------------------------------------------------------
#define H_LD 40
#define H_TILEB (128 * H_LD * 2)
#define STAGES 3
#define GEMM_SMEM (STAGES * 2 * H_TILEB)

extern __shared__ __half sgm_h[];

__device__ __forceinline__ void qkv_load_tile(uint32_t sa, uint32_t sb, int stage,
                                              const __half* Ap, const __half* Bp,
                                              int k0, int K, int tid) {
#pragma unroll
    for (int i = 0; i < 2; i++) {
        int c = tid + i * 256;
        int row = c >> 2, kc = (c & 3) * 8;
        cp_async16(sa + stage * H_TILEB + (row * H_LD + kc) * 2,
                   Ap + (size_t)row * K + k0 + kc);
    }
#pragma unroll
    for (int i = 0; i < 2; i++) {
        int c = tid + i * 256;
        int row = c >> 2, kc = (c & 3) * 8;
        cp_async16(sb + stage * H_TILEB + (row * H_LD + kc) * 2,
                   Bp + (size_t)row * K + k0 + kc);
    }
}

__global__ __launch_bounds__(256) void gemm_qkv(
    const __half* __restrict__ A, const __half* __restrict__ Bb,
    __half* __restrict__ Cb, __half* __restrict__ expqT,
    float* __restrict__ qsum, float* __restrict__ ksum,
    int K, int ldc, size_t strideB, size_t strideC) {
    uint32_t sa = (uint32_t)__cvta_generic_to_shared(sgm_h);
    uint32_t sb = sa + STAGES * H_TILEB;

    const int tid = threadIdx.x;
    const int lane = tid & 31;
    const int warp = tid >> 5;
    const int gid = lane >> 2;
    const int t4 = lane & 3;
    const int wm = warp >> 2;
    const int wn = warp & 3;
    const int t8 = lane >> 3;
    const int r8 = lane & 7;

    const __half* Ap = A + (size_t)blockIdx.y * 128 * K;
    const __half* Bp = Bb + (size_t)blockIdx.z * strideB + (size_t)blockIdx.x * 128 * K;
    __half* Cp = Cb + (size_t)blockIdx.z * strideC +
                 (size_t)blockIdx.y * 128 * ldc + (size_t)blockIdx.x * 128;

    float acc[4][4][4];
#pragma unroll
    for (int mi = 0; mi < 4; mi++)
#pragma unroll
        for (int ni = 0; ni < 4; ni++)
#pragma unroll
            for (int r = 0; r < 4; r++) acc[mi][ni][r] = 0.f;

    const int ktiles = K >> 5;
#pragma unroll
    for (int s = 0; s < STAGES - 1; s++) {
        qkv_load_tile(sa, sb, s, Ap, Bp, s * 32, K, tid);
        cp_commit();
    }
    cp_wait<STAGES - 2>();
    __syncthreads();

    for (int kt = 0; kt < ktiles; kt++) {
        uint32_t abase = sa + (kt % STAGES) * H_TILEB;
        uint32_t bbase = sb + (kt % STAGES) * H_TILEB;
#pragma unroll
        for (int kk = 0; kk < 2; kk++) {
            const int kbh = kk * 16;
            uint32_t af[4][4], bf[4][2];
#pragma unroll
            for (int mi = 0; mi < 4; mi++) {
                int row = wm * 64 + mi * 16 + r8 + (t8 & 1) * 8;
                int col = kbh + (t8 >> 1) * 8;
                ldsm_x4(af[mi], abase + (row * H_LD + col) * 2);
            }
#pragma unroll
            for (int np = 0; np < 2; np++) {
                int row = wn * 32 + np * 16 + r8 + (t8 >> 1) * 8;
                int col = kbh + (t8 & 1) * 8;
                uint32_t r4[4];
                ldsm_x4(r4, bbase + (row * H_LD + col) * 2);
                bf[np * 2][0] = r4[0]; bf[np * 2][1] = r4[1];
                bf[np * 2 + 1][0] = r4[2]; bf[np * 2 + 1][1] = r4[3];
            }
#pragma unroll
            for (int mi = 0; mi < 4; mi++)
#pragma unroll
                for (int ni = 0; ni < 4; ni++)
                    mma_f16(acc[mi][ni], af[mi], bf[ni]);
        }
        int nt = kt + STAGES - 1;
        if (nt < ktiles) {
            qkv_load_tile(sa, sb, nt % STAGES, Ap, Bp, nt * 32, K, tid);
            cp_commit();
            cp_wait<STAGES - 2>();
        } else {
            cp_wait<0>();
        }
        __syncthreads();
    }

    const int b = blockIdx.z;
    const int l0 = blockIdx.x * 128;
    const int region = blockIdx.y >> 2;

    if (region == 0) {
        // --- q: exp -> expqT[bh][l][d], per-(h,l) sums -> qsum ---
        const int h = (blockIdx.y << 1) + wm;
        __half* qtb = expqT + (((size_t)b * HEADS + h) * L + l0) * DHEAD;
        float cs0[4] = {0.f, 0.f, 0.f, 0.f};
        float cs1[4] = {0.f, 0.f, 0.f, 0.f};
#pragma unroll
        for (int mi = 0; mi < 4; mi++) {
            const int d0 = mi * 16 + gid;
#pragma unroll
            for (int ni = 0; ni < 4; ni++) {
                const int col = wn * 32 + ni * 8 + t4 * 2;
                float e0 = expf(acc[mi][ni][0]);
                float e1 = expf(acc[mi][ni][1]);
                float e2 = expf(acc[mi][ni][2]);
                float e3 = expf(acc[mi][ni][3]);
                __half* q0 = qtb + (size_t)col * DHEAD;
                __half* q1 = q0 + DHEAD;
                q0[d0] = __float2half(e0);
                q0[d0 + 8] = __float2half(e2);
                q1[d0] = __float2half(e1);
                q1[d0 + 8] = __float2half(e3);
                cs0[ni] += e0 + e2;
                cs1[ni] += e1 + e3;
            }
        }
#pragma unroll
        for (int ni = 0; ni < 4; ni++) {
            cs0[ni] += __shfl_xor_sync(0xFFFFFFFFu, cs0[ni], 4);
            cs0[ni] += __shfl_xor_sync(0xFFFFFFFFu, cs0[ni], 8);
            cs0[ni] += __shfl_xor_sync(0xFFFFFFFFu, cs0[ni], 16);
            cs1[ni] += __shfl_xor_sync(0xFFFFFFFFu, cs1[ni], 4);
            cs1[ni] += __shfl_xor_sync(0xFFFFFFFFu, cs1[ni], 8);
            cs1[ni] += __shfl_xor_sync(0xFFFFFFFFu, cs1[ni], 16);
            if (gid == 0) {
                const int col = wn * 32 + ni * 8 + t4 * 2;
                float* qs = qsum + ((size_t)b * HEADS + h) * L + l0 + col;
                qs[0] = cs0[ni];
                qs[1] = cs1[ni];
            }
        }
    } else if (region == 1) {
        // --- k: exp in place + per-row sums (atomic) ---
#pragma unroll
        for (int mi = 0; mi < 4; mi++) {
            const int r0 = wm * 64 + mi * 16 + gid;
            float rs0 = 0.f, rs1 = 0.f;
#pragma unroll
            for (int ni = 0; ni < 4; ni++) {
                const int col = wn * 32 + ni * 8 + t4 * 2;
                float e0 = expf(acc[mi][ni][0]);
                float e1 = expf(acc[mi][ni][1]);
                float e2 = expf(acc[mi][ni][2]);
                float e3 = expf(acc[mi][ni][3]);
                *(__half2*)&Cp[(size_t)r0 * ldc + col] = __floats2half2_rn(e0, e1);
                *(__half2*)&Cp[(size_t)(r0 + 8) * ldc + col] = __floats2half2_rn(e2, e3);
                rs0 += e0 + e1;
                rs1 += e2 + e3;
            }
            rs0 += __shfl_xor_sync(0xFFFFFFFFu, rs0, 1);
            rs0 += __shfl_xor_sync(0xFFFFFFFFu, rs0, 2);
            rs1 += __shfl_xor_sync(0xFFFFFFFFu, rs1, 1);
            rs1 += __shfl_xor_sync(0xFFFFFFFFu, rs1, 2);
            if (t4 == 0) {
                const int ch = (blockIdx.y - 4) * 128 + r0;
                atomicAdd(&ksum[(size_t)b * HIDDEN + ch], rs0);
                atomicAdd(&ksum[(size_t)b * HIDDEN + ch + 8], rs1);
            }
        }
    } else {
        // --- v: plain fp16 store ---
#pragma unroll
        for (int mi = 0; mi < 4; mi++) {
            const int r0 = wm * 64 + mi * 16 + gid;
#pragma unroll
            for (int ni = 0; ni < 4; ni++) {
                const int col = wn * 32 + ni * 8 + t4 * 2;
                *(__half2*)&Cp[(size_t)r0 * ldc + col] =
                    __floats2half2_rn(acc[mi][ni][0], acc[mi][ni][1]);
                *(__half2*)&Cp[(size_t)(r0 + 8) * ldc + col] =
                    __floats2half2_rn(acc[mi][ni][2], acc[mi][ni][3]);
            }
        }
    }
}

// ---------------------------------------------------------------------------
// ctx partial via HMMA (fp32 accum):
// ctxp[chunk][bh] = expk[64, 512chunk] @ v[64, 512chunk]^T
// ---------------------------------------------------------------------------
#define CTX_LD 40
#define CTX_TILEB (64 * CTX_LD * 2)

__global__ __launch_bounds__(128) void ctx_part_mma(const __half* __restrict__ qkvh,
                                                    float* __restrict__ ctxp) {
    __shared__ __half csk[3 * 64 * CTX_LD];
    __shared__ __half csv[3 * 64 * CTX_LD];
    uint32_t ska = (uint32_t)__cvta_generic_to_shared(csk);
    uint32_t skv = (uint32_t)__cvta_generic_to_shared(csv);

    int bh = blockIdx.x;
    int chunk = blockIdx.y;
    int b = bh >> 3, h = bh & 7;
    const __half* kp = qkvh + ((size_t)b * QKV_CH + HIDDEN + h * DHEAD) * L;
    const __half* vp = qkvh + ((size_t)b * QKV_CH + 2 * HIDDEN + h * DHEAD) * L;
    const int lbeg = chunk * (L / NCHUNK);

    const int tid = threadIdx.x;
    const int lane = tid & 31;
    const int warp = tid >> 5;
    const int gid = lane >> 2;
    const int t4 = lane & 3;
    const int t8 = lane >> 3;
    const int r8 = lane & 7;

    auto load_stage = [&](int stage, int kt) {
        int l0 = lbeg + kt * 32;
#pragma unroll
        for (int i = 0; i < 2; i++) {
            int flat = i * 128 + tid;
            int row = flat >> 2, kc = (flat & 3) * 8;
            cp_async16(ska + stage * CTX_TILEB + (row * CTX_LD + kc) * 2,
                       kp + (size_t)row * L + l0 + kc);
            cp_async16(skv + stage * CTX_TILEB + (row * CTX_LD + kc) * 2,
                       vp + (size_t)row * L + l0 + kc);
        }
    };

    float acc[8][4];
#pragma unroll
    for (int ni = 0; ni < 8; ni++)
#pragma unroll
        for (int r = 0; r < 4; r++) acc[ni][r] = 0.f;

    const int ktiles = (L / NCHUNK) >> 5;
#pragma unroll
    for (int s = 0; s < 2; s++) {
        load_stage(s, s);
        cp_commit();
    }
    cp_wait<1>();
    __syncthreads();

    for (int kt = 0; kt < ktiles; kt++) {
        uint32_t abase = ska + (kt % 3) * CTX_TILEB;
        uint32_t bbase = skv + (kt % 3) * CTX_TILEB;
#pragma unroll
        for (int kk = 0; kk < 2; kk++) {
            const int kbh = kk * 16;
            uint32_t af[4], bf[8][2];
            {
                int row = warp * 16 + r8 + (t8 & 1) * 8;
                int col = kbh + (t8 >> 1) * 8;
                ldsm_x4(af, abase + (row * CTX_LD + col) * 2);
            }
#pragma unroll
            for (int np = 0; np < 4; np++) {
                int row = np * 16 + r8 + (t8 >> 1) * 8;
                int col = kbh + (t8 & 1) * 8;
                uint32_t r4[4];
                ldsm_x4(r4, bbase + (row * CTX_LD + col) * 2);
                bf[np * 2][0] = r4[0]; bf[np * 2][1] = r4[1];
                bf[np * 2 + 1][0] = r4[2]; bf[np * 2 + 1][1] = r4[3];
            }
#pragma unroll
            for (int ni = 0; ni < 8; ni++)
                mma_f16(acc[ni], af, bf[ni]);
        }
        int nt = kt + 2;
        if (nt < ktiles) {
            load_stage(nt % 3, nt);
            cp_commit();
            cp_wait<1>();
        } else {
            cp_wait<0>();
        }
        __syncthreads();
    }

    float* cp = ctxp + ((size_t)chunk * BH + bh) * (DHEAD * DHEAD);
    int d = warp * 16 + gid;
#pragma unroll
    for (int ni = 0; ni < 8; ni++) {
        int col = ni * 8 + t4 * 2;
        *(float2*)&cp[d * DHEAD + col] = make_float2(acc[ni][0], acc[ni][1]);
        *(float2*)&cp[(d + 8) * DHEAD + col] = make_float2(acc[ni][2], acc[ni][3]);
    }
}

// ---------------------------------------------------------------------------
// Reduce chunks + divide by ksum, emit ctxh fp16 transposed [bh][e][d]
// ---------------------------------------------------------------------------
__global__ void ctx_reduce_kernel(const float* __restrict__ ctxp,
                                  const float* __restrict__ ksum,
                                  __half* __restrict__ ctxh) {
    int i = blockIdx.x * 256 + threadIdx.x; // over BH*4096
    int bh = i >> 12;
    int rem = i & 4095;
    int d = rem >> 6, e = rem & 63;
    float s = 0.f;
#pragma unroll
    for (int c = 0; c < NCHUNK; c++)
        s += ctxp[(size_t)c * (BH * DHEAD * DHEAD) + i];
    int b = bh >> 3, h = bh & 7;
    float kv = ksum[(size_t)b * HIDDEN + h * DHEAD + d];
    ctxh[((size_t)bh << 12) + e * DHEAD + d] = __float2half(s / kv);
}

// ---------------------------------------------------------------------------
// attn via HMMA: attnT[l][h*64+e] = (scale/qsum[l]) * sum_d expq[l][d]*ctxh[e][d]
// ---------------------------------------------------------------------------
#define AQ_LD 72
__global__ __launch_bounds__(128) void attn_mma(const __half* __restrict__ expqT,
                                                const float* __restrict__ qsum,
                                                const __half* __restrict__ ctxh,
                                                __half* __restrict__ attnT) {
    __shared__ __half As[128 * AQ_LD];
    __shared__ __half Bs[64 * AQ_LD];
    uint32_t sa = (uint32_t)__cvta_generic_to_shared(As);
    uint32_t sb = (uint32_t)__cvta_generic_to_shared(Bs);

    const int l0 = blockIdx.x * 128;
    const int bh = blockIdx.y;
    const int b = bh >> 3, h = bh & 7;

    const int tid = threadIdx.x;
    const int lane = tid & 31;
    const int warp = tid >> 5;
    const int gid = lane >> 2;
    const int t4 = lane & 3;
    const int t8 = lane >> 3;
    const int r8 = lane & 7;
    const int wm = warp >> 1;
    const int wn = warp & 1;

    const __half* qp = expqT + ((size_t)bh * L + l0) * DHEAD;
    const __half* cp = ctxh + ((size_t)bh << 12);

#pragma unroll
    for (int i = 0; i < 8; i++) {
        int flat = i * 128 + tid;
        int row = flat >> 3, seg = flat & 7;
        cp_async16(sa + (row * AQ_LD + seg * 8) * 2, qp + (size_t)row * DHEAD + seg * 8);
    }
#pragma unroll
    for (int i = 0; i < 4; i++) {
        int flat = i * 128 + tid;
        int row = flat >> 3, seg = flat & 7;
        cp_async16(sb + (row * AQ_LD + seg * 8) * 2, cp + (size_t)row * DHEAD + seg * 8);
    }
    cp_commit();
    cp_wait<0>();
    __syncthreads();

    float acc[4][4][4];
#pragma unroll
    for (int mi = 0; mi < 4; mi++)
#pragma unroll
        for (int ni = 0; ni < 4; ni++)
#pragma unroll
            for (int r = 0; r < 4; r++) acc[mi][ni][r] = 0.f;

#pragma unroll
    for (int kt = 0; kt < 4; kt++) {
        const int kbh = kt * 16;
        uint32_t af[4][4], bf[4][2];
#pragma unroll
        for (int mi = 0; mi < 4; mi++) {
            int row = wm * 64 + mi * 16 + r8 + (t8 & 1) * 8;
            int col = kbh + (t8 >> 1) * 8;
            ldsm_x4(af[mi], sa + (row * AQ_LD + col) * 2);
        }
#pragma unroll
        for (int np = 0; np < 2; np++) {
            int row = wn * 32 + np * 16 + r8 + (t8 >> 1) * 8;
            int col = kbh + (t8 & 1) * 8;
            uint32_t r4[4];
            ldsm_x4(r4, sb + (row * AQ_LD + col) * 2);
            bf[np * 2][0] = r4[0]; bf[np * 2][1] = r4[1];
            bf[np * 2 + 1][0] = r4[2]; bf[np * 2 + 1][1] = r4[3];
        }
#pragma unroll
        for (int mi = 0; mi < 4; mi++)
#pragma unroll
            for (int ni = 0; ni < 4; ni++)
                mma_f16(acc[mi][ni], af[mi], bf[ni]);
    }

    const float* qs = qsum + (size_t)bh * L + l0;
#pragma unroll
    for (int mi = 0; mi < 4; mi++) {
        const int r0 = wm * 64 + mi * 16 + gid;
        const float inv0 = ATTN_SCALE / qs[r0];
        const float inv1 = ATTN_SCALE / qs[r0 + 8];
        __half* o0 = attnT + ((size_t)b * L + l0 + r0) * HIDDEN + h * DHEAD;
        __half* o1 = attnT + ((size_t)b * L + l0 + r0 + 8) * HIDDEN + h * DHEAD;
#pragma unroll
        for (int ni = 0; ni < 4; ni++) {
            const int col = wn * 32 + ni * 8 + t4 * 2;
            *(__half2*)&o0[col] = __floats2half2_rn(acc[mi][ni][0] * inv0,
                                                    acc[mi][ni][1] * inv0);
            *(__half2*)&o1[col] = __floats2half2_rn(acc[mi][ni][2] * inv1,
                                                    acc[mi][ni][3] * inv1);
        }
    }
}

// ---------------------------------------------------------------------------
// Fused out-GEMM + bias + channel RMSNorm + residual.
// ---------------------------------------------------------------------------
#define OA_BYTES (512 * H_LD * 2)
#define OB_BYTES (64 * H_LD * 2)
#define OSTG_BYTES (OA_BYTES + OB_BYTES)
#define OSTAGES 3
#define XS_OFF (OSTAGES * OSTG_BYTES)
#define XS_LDF 68
#define OUT_SMEM (XS_OFF + 256 * XS_LDF * 4)

__global__ __launch_bounds__(512) void gemm_out_fused(
    const __half* __restrict__ A, const __half* __restrict__ Bb,
    const float* __restrict__ bias, const float* __restrict__ gout,
    const float* __restrict__ x, float* __restrict__ out) {
    __shared__ float colsum[64];
    uint32_t sbase = (uint32_t)__cvta_generic_to_shared(sgm_h);
    float* xs = (float*)((char*)sgm_h + XS_OFF);

    const int tid = threadIdx.x;
    const int lane = tid & 31;
    const int warp = tid >> 5;
    const int gid = lane >> 2;
    const int t4 = lane & 3;
    const int t8 = lane >> 3;
    const int r8 = lane & 7;
    const int bz = blockIdx.y;
    const int l0 = blockIdx.x * 64;

    const __half* Bp = Bb + ((size_t)bz * L + l0) * HIDDEN;

    float acc[2][8][4];
#pragma unroll
    for (int mi = 0; mi < 2; mi++)
#pragma unroll
        for (int ni = 0; ni < 8; ni++)
#pragma unroll
            for (int r = 0; r < 4; r++) acc[mi][ni][r] = 0.f;

    auto load_stage = [&](int kt) {
        uint32_t sA = sbase + (kt % OSTAGES) * OSTG_BYTES;
        uint32_t sB = sA + OA_BYTES;
        int k0 = kt * 32;
#pragma unroll
        for (int i = 0; i < 4; i++) {
            int c = tid + i * 512;
            int row = c >> 2, kc = (c & 3) * 8;
            cp_async16(sA + (row * H_LD + kc) * 2, A + (size_t)row * HIDDEN + k0 + kc);
        }
        if (tid < 256) {
            int row = tid >> 2, kc = (tid & 3) * 8;
            cp_async16(sB + (row * H_LD + kc) * 2, Bp + (size_t)row * HIDDEN + k0 + kc);
        }
    };
    auto load_xchunk = [&](int c) {
        if (tid < 256) {
            int flat = c * 256 + tid;
            int row = flat >> 4, seg = flat & 15;
            cp_async16(sbase + XS_OFF + row * (XS_LDF * 4) + seg * 16,
                       x + ((size_t)bz * C + row) * L + l0 + seg * 4);
        }
    };

    const int ktiles = HIDDEN >> 5;
#pragma unroll
    for (int s = 0; s < OSTAGES - 1; s++) {
        load_stage(s);
        load_xchunk(s);
        cp_commit();
    }
    cp_wait<OSTAGES - 2>();
    __syncthreads();

    for (int kt = 0; kt < ktiles; kt++) {
        uint32_t abase = sbase + (kt % OSTAGES) * OSTG_BYTES;
        uint32_t bbase = abase + OA_BYTES;
#pragma unroll
        for (int kk = 0; kk < 2; kk++) {
            const int kbh = kk * 16;
            uint32_t af[2][4], bf[8][2];
#pragma unroll
            for (int mi = 0; mi < 2; mi++) {
                int row = warp * 32 + mi * 16 + r8 + (t8 & 1) * 8;
                int col = kbh + (t8 >> 1) * 8;
                ldsm_x4(af[mi], abase + (row * H_LD + col) * 2);
            }
#pragma unroll
            for (int np = 0; np < 4; np++) {
                int row = np * 16 + r8 + (t8 >> 1) * 8;
                int col = kbh + (t8 & 1) * 8;
                uint32_t r4[4];
                ldsm_x4(r4, bbase + (row * H_LD + col) * 2);
                bf[np * 2][0] = r4[0]; bf[np * 2][1] = r4[1];
                bf[np * 2 + 1][0] = r4[2]; bf[np * 2 + 1][1] = r4[3];
            }
#pragma unroll
            for (int mi = 0; mi < 2; mi++)
#pragma unroll
                for (int ni = 0; ni < 8; ni++)
                    mma_f16(acc[mi][ni], af[mi], bf[ni]);
        }
        int nt = kt + OSTAGES - 1;
        if (nt < ktiles) {
            load_stage(nt);
            load_xchunk(nt);
            cp_commit();
            cp_wait<OSTAGES - 2>();
        } else {
            cp_wait<0>();
        }
        __syncthreads();
    }

    float bvs[2][2];
#pragma unroll
    for (int mi = 0; mi < 2; mi++) {
        int r0 = warp * 32 + mi * 16 + gid;
        bvs[mi][0] = bias[r0];
        bvs[mi][1] = bias[r0 + 8];
    }
    if (tid < 64) colsum[tid] = 0.f;
    __syncthreads();

#pragma unroll
    for (int ni = 0; ni < 8; ni++) {
#pragma unroll
        for (int c01 = 0; c01 < 2; c01++) {
            float part = 0.f;
#pragma unroll
            for (int mi = 0; mi < 2; mi++) {
                float v0 = acc[mi][ni][c01] + bvs[mi][0];
                float v1 = acc[mi][ni][2 + c01] + bvs[mi][1];
                acc[mi][ni][c01] = v0;
                acc[mi][ni][2 + c01] = v1;
                part += v0 * v0 + v1 * v1;
            }
            part += __shfl_xor_sync(0xFFFFFFFFu, part, 4);
            part += __shfl_xor_sync(0xFFFFFFFFu, part, 8);
            part += __shfl_xor_sync(0xFFFFFFFFu, part, 16);
            if (gid == 0) atomicAdd(&colsum[ni * 8 + t4 * 2 + c01], part);
        }
    }
    __syncthreads();

    float scl[8][2];
#pragma unroll
    for (int ni = 0; ni < 8; ni++) {
        int col = ni * 8 + t4 * 2;
        scl[ni][0] = SQRT_C / fmaxf(sqrtf(colsum[col]), 1e-12f);
        scl[ni][1] = SQRT_C / fmaxf(sqrtf(colsum[col + 1]), 1e-12f);
    }

#pragma unroll
    for (int mi = 0; mi < 2; mi++) {
        int r0 = warp * 32 + mi * 16 + gid;
        float g0 = gout[r0], g1 = gout[r0 + 8];
        const float* xr0;
        const float* xr1;
        if (r0 + 8 < 256) {
            xr0 = xs + r0 * XS_LDF;
            xr1 = xs + (r0 + 8) * XS_LDF;
        } else {
            xr0 = x + ((size_t)bz * C + r0) * L + l0;
            xr1 = x + ((size_t)bz * C + r0 + 8) * L + l0;
        }
        float* or0 = out + ((size_t)bz * C + r0) * L + l0;
        float* or1 = out + ((size_t)bz * C + r0 + 8) * L + l0;
#pragma unroll
        for (int ni = 0; ni < 8; ni++) {
            int col = ni * 8 + t4 * 2;
            float2 xv0 = *(const float2*)&xr0[col];
            float2 xv1 = *(const float2*)&xr1[col];
            float2 v0 = make_float2(acc[mi][ni][0] * scl[ni][0] * g0 + xv0.x,
                                    acc[mi][ni][1] * scl[ni][1] * g0 + xv0.y);
            float2 v1 = make_float2(acc[mi][ni][2] * scl[ni][0] * g1 + xv1.x,
                                    acc[mi][ni][3] * scl[ni][1] * g1 + xv1.y);
            *(float2*)&or0[col] = v0;
            *(float2*)&or1[col] = v1;
        }
    }
}

// ---------------------------------------------------------------------------
extern "C" void kernel_launch(void* const* d_in, const int* in_sizes, int n_in,
                              void* d_out, int out_size) {
    const float* x     = (const float*)d_in[0];
    const float* g_in  = (const float*)d_in[1];
    const float* w_qkv = (const float*)d_in[2];
    const float* w_out = (const float*)d_in[3];
    const float* b_out = (const float*)d_in[4];
    const float* g_out = (const float*)d_in[5];
    float* out = (float*)d_out;

    __half *w2h, *wouth, *xhT, *qkvh, *expqT, *ctxh, *attnT;
    float *qsum, *ksum, *ctxp;
    cudaGetSymbolAddress((void**)&w2h, g_w2h);
    cudaGetSymbolAddress((void**)&wouth, g_wouth);
    cudaGetSymbolAddress((void**)&xhT, g_xhT);
    cudaGetSymbolAddress((void**)&qkvh, g_qkvh);
    cudaGetSymbolAddress((void**)&expqT, g_expqT);
    cudaGetSymbolAddress((void**)&qsum, g_qsum);
    cudaGetSymbolAddress((void**)&ksum, g_ksum);
    cudaGetSymbolAddress((void**)&ctxp, g_ctxp);
    cudaGetSymbolAddress((void**)&ctxh, g_ctxh);
    cudaGetSymbolAddress((void**)&attnT, g_attnT);

    cudaFuncSetAttribute(gemm_qkv, cudaFuncAttributeMaxDynamicSharedMemorySize,
                         GEMM_SMEM);
    cudaFuncSetAttribute(gemm_out_fused, cudaFuncAttributeMaxDynamicSharedMemorySize,
                         OUT_SMEM);

    // 0. merged prologue: weight conversions + ksum zero
    prologue_kernel<<<(QKV_CH * C) / 256, 256>>>(w_qkv, g_in, w_out,
                                                 w2h, wouth, ksum);

    // 1. fused rmsnorm scale + transpose -> xhT fp16 (fp16 staging)
    normxpose_kernel<<<dim3(L / 32, B), 256>>>(x, xhT);

    // 2. qkv GEMM (fp32 accum) with fused exp epilogues
    gemm_qkv<<<dim3(L / 128, QKV_CH / 128, B), 256, GEMM_SMEM>>>(
        w2h, xhT, qkvh, expqT, qsum, ksum, C, L,
        (size_t)L * C, (size_t)QKV_CH * L);

    // 3. context partials via HMMA (fp32 accum), reduce + /ksum -> ctxh
    ctx_part_mma<<<dim3(BH, NCHUNK), 128>>>(qkvh, ctxp);
    ctx_reduce_kernel<<<(BH * DHEAD * DHEAD) / 256, 256>>>(ctxp, ksum, ctxh);

    // 4. attn via HMMA -> attnT
    attn_mma<<<dim3(L / 128, BH), 128>>>(expqT, qsum, ctxh, attnT);

    // 5. out = rmsnorm(wouth @ attn + b_out)*g_out + x
    gemm_out_fused<<<dim3(L / 64, B), 512, OUT_SMEM>>>(
        wouth, attnT, b_out, g_out, x, out);
}

// round 14
// speedup vs baseline: 1.3035x; 1.0181x over previous
#include <cuda_runtime.h>
#include <cuda_fp16.h>
#include <math.h>
#include <stdint.h>

// Problem constants
#define B 8
#define C 512
#define L 4096
#define HEADS 8
#define DHEAD 64
#define HIDDEN 512           // HEADS*DHEAD
#define QKV_CH 1536          // 3*HIDDEN
#define SQRT_C 22.627416998f // sqrt(512)
#define ATTN_SCALE 0.125f    // 64^-0.5
#define NCHUNK 8             // ctx split factor over L
#define BH (B * HEADS)

// Scratch buffers
__device__ __half g_w2h[(size_t)QKV_CH * C];        // w_qkv * g_in, fp16
__device__ __half g_wouth[(size_t)C * HIDDEN];
__device__ __half g_xhT[(size_t)B * L * C];         // (x*s)^T fp16 [b][l][c]
__device__ __half g_qkvh[(size_t)B * QKV_CH * L];   // fp16 [b][ch][l]; k rows hold exp(k)
__device__ __half g_expqT[(size_t)BH * L * DHEAD];  // exp(q) [bh][l][d]
__device__ float  g_qsum[(size_t)BH * L];           // per-(bh,l) sum of exp(q) over d
__device__ float  g_ksum[(size_t)B * HIDDEN];       // per-(b,kch) sum of exp(k) over l
__device__ float  g_ctxp[(size_t)NCHUNK * BH * DHEAD * DHEAD];
__device__ __half g_ctxh[(size_t)BH * DHEAD * DHEAD]; // ctx^T/ksum fp16 [bh][e][d]

// ---------------------------------------------------------------------------
// PTX helpers
// ---------------------------------------------------------------------------
__device__ __forceinline__ void cp_async16(uint32_t dst, const void* src) {
    asm volatile("cp.async.cg.shared.global [%0], [%1], 16;" :: "r"(dst), "l"(src));
}
__device__ __forceinline__ void cp_commit() {
    asm volatile("cp.async.commit_group;");
}
template <int N>
__device__ __forceinline__ void cp_wait() {
    asm volatile("cp.async.wait_group %0;" :: "n"(N));
}
__device__ __forceinline__ void ldsm_x4(uint32_t r[4], uint32_t addr) {
    asm volatile("ldmatrix.sync.aligned.m8n8.x4.shared.b16 {%0,%1,%2,%3}, [%4];"
                 : "=r"(r[0]), "=r"(r[1]), "=r"(r[2]), "=r"(r[3]) : "r"(addr));
}
__device__ __forceinline__ void mma_f16(float d[4], const uint32_t a[4],
                                        const uint32_t b[2]) {
    asm volatile(
        "mma.sync.aligned.m16n8k16.row.col.f32.f16.f16.f32 "
        "{%0,%1,%2,%3}, {%4,%5,%6,%7}, {%8,%9}, {%0,%1,%2,%3};"
        : "+f"(d[0]), "+f"(d[1]), "+f"(d[2]), "+f"(d[3])
        : "r"(a[0]), "r"(a[1]), "r"(a[2]), "r"(a[3]),
          "r"(b[0]), "r"(b[1]));
}

// ---------------------------------------------------------------------------
// Merged prologue: w2h, wouth conversions + ksum zero (one launch)
// ---------------------------------------------------------------------------
__global__ void prologue_kernel(const float* __restrict__ w_qkv,
                                const float* __restrict__ g_in,
                                const float* __restrict__ w_out,
                                __half* __restrict__ w2h,
                                __half* __restrict__ wouth,
                                float* __restrict__ ksum) {
    int i = blockIdx.x * 256 + threadIdx.x;
    w2h[i] = __float2half(w_qkv[i] * g_in[i & (C - 1)]);
    if (i < C * HIDDEN) wouth[i] = __float2half(w_out[i]);
    if (i < B * HIDDEN) ksum[i] = 0.f;
}

// ---------------------------------------------------------------------------
// Fused rmsnorm-scale + transpose: xhT[b][l][c] = fp16(x[b][c][l] * s[b,l])
// ---------------------------------------------------------------------------
#define NXS 34
__global__ __launch_bounds__(256) void normxpose_kernel(const float* __restrict__ x,
                                                        __half* __restrict__ xhT) {
    __shared__ __half t[512 * NXS];   // t[c*NXS + l]
    __shared__ float ssred[8][32];
    __shared__ float sc[32];
    int b = blockIdx.y;
    int l0 = blockIdx.x * 32;
    int tid = threadIdx.x;
    int l = tid & 31;
    const float* xp = x + ((size_t)b * C) * L + l0;
    float ss = 0.f;
#pragma unroll
    for (int i = 0; i < 64; i++) {
        int c = i * 8 + (tid >> 5);
        float v = xp[(size_t)c * L + l];
        ss += v * v;
        t[c * NXS + l] = __float2half(v);
    }
    ssred[tid >> 5][l] = ss;
    __syncthreads();
    if (tid < 32) {
        float s = 0.f;
#pragma unroll
        for (int j = 0; j < 8; j++) s += ssred[j][tid];
        sc[tid] = SQRT_C / fmaxf(sqrtf(s), 1e-12f);
    }
    __syncthreads();
    __half* op = xhT + ((size_t)b * L + l0) * C;
#pragma unroll
    for (int i = 0; i < 64; i++) {
        int flat = i * 256 + tid;
        int lo = flat >> 9, c = flat & 511;
        op[(size_t)lo * C + c] =
            __float2half(__half2float(t[c * NXS + lo]) * sc[lo]);
    }
}

// ---------------------------------------------------------------------------
// QKV GEMM: 128x128x32, 8 warps (2x4) of 64x32, 3-stage cp.async, fp32 accum.
// Region-specialized epilogue.
// ---------------------------------------------------------------------------
#define H_LD 40
#define H_TILEB (128 * H_LD * 2)
#define STAGES 3
#define GEMM_SMEM (STAGES * 2 * H_TILEB)

extern __shared__ __half sgm_h[];

__device__ __forceinline__ void qkv_load_tile(uint32_t sa, uint32_t sb, int stage,
                                              const __half* Ap, const __half* Bp,
                                              int k0, int K, int tid) {
#pragma unroll
    for (int i = 0; i < 2; i++) {
        int c = tid + i * 256;
        int row = c >> 2, kc = (c & 3) * 8;
        cp_async16(sa + stage * H_TILEB + (row * H_LD + kc) * 2,
                   Ap + (size_t)row * K + k0 + kc);
    }
#pragma unroll
    for (int i = 0; i < 2; i++) {
        int c = tid + i * 256;
        int row = c >> 2, kc = (c & 3) * 8;
        cp_async16(sb + stage * H_TILEB + (row * H_LD + kc) * 2,
                   Bp + (size_t)row * K + k0 + kc);
    }
}

__global__ __launch_bounds__(256) void gemm_qkv(
    const __half* __restrict__ A, const __half* __restrict__ Bb,
    __half* __restrict__ Cb, __half* __restrict__ expqT,
    float* __restrict__ qsum, float* __restrict__ ksum,
    int K, int ldc, size_t strideB, size_t strideC) {
    uint32_t sa = (uint32_t)__cvta_generic_to_shared(sgm_h);
    uint32_t sb = sa + STAGES * H_TILEB;

    const int tid = threadIdx.x;
    const int lane = tid & 31;
    const int warp = tid >> 5;
    const int gid = lane >> 2;
    const int t4 = lane & 3;
    const int wm = warp >> 2;
    const int wn = warp & 3;
    const int t8 = lane >> 3;
    const int r8 = lane & 7;

    const __half* Ap = A + (size_t)blockIdx.y * 128 * K;
    const __half* Bp = Bb + (size_t)blockIdx.z * strideB + (size_t)blockIdx.x * 128 * K;
    __half* Cp = Cb + (size_t)blockIdx.z * strideC +
                 (size_t)blockIdx.y * 128 * ldc + (size_t)blockIdx.x * 128;

    float acc[4][4][4];
#pragma unroll
    for (int mi = 0; mi < 4; mi++)
#pragma unroll
        for (int ni = 0; ni < 4; ni++)
#pragma unroll
            for (int r = 0; r < 4; r++) acc[mi][ni][r] = 0.f;

    const int ktiles = K >> 5;
#pragma unroll
    for (int s = 0; s < STAGES - 1; s++) {
        qkv_load_tile(sa, sb, s, Ap, Bp, s * 32, K, tid);
        cp_commit();
    }
    cp_wait<STAGES - 2>();
    __syncthreads();

    for (int kt = 0; kt < ktiles; kt++) {
        uint32_t abase = sa + (kt % STAGES) * H_TILEB;
        uint32_t bbase = sb + (kt % STAGES) * H_TILEB;
#pragma unroll
        for (int kk = 0; kk < 2; kk++) {
            const int kbh = kk * 16;
            uint32_t af[4][4], bf[4][2];
#pragma unroll
            for (int mi = 0; mi < 4; mi++) {
                int row = wm * 64 + mi * 16 + r8 + (t8 & 1) * 8;
                int col = kbh + (t8 >> 1) * 8;
                ldsm_x4(af[mi], abase + (row * H_LD + col) * 2);
            }
#pragma unroll
            for (int np = 0; np < 2; np++) {
                int row = wn * 32 + np * 16 + r8 + (t8 >> 1) * 8;
                int col = kbh + (t8 & 1) * 8;
                uint32_t r4[4];
                ldsm_x4(r4, bbase + (row * H_LD + col) * 2);
                bf[np * 2][0] = r4[0]; bf[np * 2][1] = r4[1];
                bf[np * 2 + 1][0] = r4[2]; bf[np * 2 + 1][1] = r4[3];
            }
#pragma unroll
            for (int mi = 0; mi < 4; mi++)
#pragma unroll
                for (int ni = 0; ni < 4; ni++)
                    mma_f16(acc[mi][ni], af[mi], bf[ni]);
        }
        int nt = kt + STAGES - 1;
        if (nt < ktiles) {
            qkv_load_tile(sa, sb, nt % STAGES, Ap, Bp, nt * 32, K, tid);
            cp_commit();
            cp_wait<STAGES - 2>();
        } else {
            cp_wait<0>();
        }
        __syncthreads();
    }

    const int b = blockIdx.z;
    const int l0 = blockIdx.x * 128;
    const int region = blockIdx.y >> 2;

    if (region == 0) {
        const int h = (blockIdx.y << 1) + wm;
        __half* qtb = expqT + (((size_t)b * HEADS + h) * L + l0) * DHEAD;
        float cs0[4] = {0.f, 0.f, 0.f, 0.f};
        float cs1[4] = {0.f, 0.f, 0.f, 0.f};
#pragma unroll
        for (int mi = 0; mi < 4; mi++) {
            const int d0 = mi * 16 + gid;
#pragma unroll
            for (int ni = 0; ni < 4; ni++) {
                const int col = wn * 32 + ni * 8 + t4 * 2;
                float e0 = expf(acc[mi][ni][0]);
                float e1 = expf(acc[mi][ni][1]);
                float e2 = expf(acc[mi][ni][2]);
                float e3 = expf(acc[mi][ni][3]);
                __half* q0 = qtb + (size_t)col * DHEAD;
                __half* q1 = q0 + DHEAD;
                q0[d0] = __float2half(e0);
                q0[d0 + 8] = __float2half(e2);
                q1[d0] = __float2half(e1);
                q1[d0 + 8] = __float2half(e3);
                cs0[ni] += e0 + e2;
                cs1[ni] += e1 + e3;
            }
        }
#pragma unroll
        for (int ni = 0; ni < 4; ni++) {
            cs0[ni] += __shfl_xor_sync(0xFFFFFFFFu, cs0[ni], 4);
            cs0[ni] += __shfl_xor_sync(0xFFFFFFFFu, cs0[ni], 8);
            cs0[ni] += __shfl_xor_sync(0xFFFFFFFFu, cs0[ni], 16);
            cs1[ni] += __shfl_xor_sync(0xFFFFFFFFu, cs1[ni], 4);
            cs1[ni] += __shfl_xor_sync(0xFFFFFFFFu, cs1[ni], 8);
            cs1[ni] += __shfl_xor_sync(0xFFFFFFFFu, cs1[ni], 16);
            if (gid == 0) {
                const int col = wn * 32 + ni * 8 + t4 * 2;
                float* qs = qsum + ((size_t)b * HEADS + h) * L + l0 + col;
                qs[0] = cs0[ni];
                qs[1] = cs1[ni];
            }
        }
    } else if (region == 1) {
#pragma unroll
        for (int mi = 0; mi < 4; mi++) {
            const int r0 = wm * 64 + mi * 16 + gid;
            float rs0 = 0.f, rs1 = 0.f;
#pragma unroll
            for (int ni = 0; ni < 4; ni++) {
                const int col = wn * 32 + ni * 8 + t4 * 2;
                float e0 = expf(acc[mi][ni][0]);
                float e1 = expf(acc[mi][ni][1]);
                float e2 = expf(acc[mi][ni][2]);
                float e3 = expf(acc[mi][ni][3]);
                *(__half2*)&Cp[(size_t)r0 * ldc + col] = __floats2half2_rn(e0, e1);
                *(__half2*)&Cp[(size_t)(r0 + 8) * ldc + col] = __floats2half2_rn(e2, e3);
                rs0 += e0 + e1;
                rs1 += e2 + e3;
            }
            rs0 += __shfl_xor_sync(0xFFFFFFFFu, rs0, 1);
            rs0 += __shfl_xor_sync(0xFFFFFFFFu, rs0, 2);
            rs1 += __shfl_xor_sync(0xFFFFFFFFu, rs1, 1);
            rs1 += __shfl_xor_sync(0xFFFFFFFFu, rs1, 2);
            if (t4 == 0) {
                const int ch = (blockIdx.y - 4) * 128 + r0;
                atomicAdd(&ksum[(size_t)b * HIDDEN + ch], rs0);
                atomicAdd(&ksum[(size_t)b * HIDDEN + ch + 8], rs1);
            }
        }
    } else {
#pragma unroll
        for (int mi = 0; mi < 4; mi++) {
            const int r0 = wm * 64 + mi * 16 + gid;
#pragma unroll
            for (int ni = 0; ni < 4; ni++) {
                const int col = wn * 32 + ni * 8 + t4 * 2;
                *(__half2*)&Cp[(size_t)r0 * ldc + col] =
                    __floats2half2_rn(acc[mi][ni][0], acc[mi][ni][1]);
                *(__half2*)&Cp[(size_t)(r0 + 8) * ldc + col] =
                    __floats2half2_rn(acc[mi][ni][2], acc[mi][ni][3]);
            }
        }
    }
}

// ---------------------------------------------------------------------------
// ctx partial via HMMA (fp32 accum)
// ---------------------------------------------------------------------------
#define CTX_LD 40
#define CTX_TILEB (64 * CTX_LD * 2)

__global__ __launch_bounds__(128) void ctx_part_mma(const __half* __restrict__ qkvh,
                                                    float* __restrict__ ctxp) {
    __shared__ __half csk[3 * 64 * CTX_LD];
    __shared__ __half csv[3 * 64 * CTX_LD];
    uint32_t ska = (uint32_t)__cvta_generic_to_shared(csk);
    uint32_t skv = (uint32_t)__cvta_generic_to_shared(csv);

    int bh = blockIdx.x;
    int chunk = blockIdx.y;
    int b = bh >> 3, h = bh & 7;
    const __half* kp = qkvh + ((size_t)b * QKV_CH + HIDDEN + h * DHEAD) * L;
    const __half* vp = qkvh + ((size_t)b * QKV_CH + 2 * HIDDEN + h * DHEAD) * L;
    const int lbeg = chunk * (L / NCHUNK);

    const int tid = threadIdx.x;
    const int lane = tid & 31;
    const int warp = tid >> 5;
    const int gid = lane >> 2;
    const int t4 = lane & 3;
    const int t8 = lane >> 3;
    const int r8 = lane & 7;

    auto load_stage = [&](int stage, int kt) {
        int l0 = lbeg + kt * 32;
#pragma unroll
        for (int i = 0; i < 2; i++) {
            int flat = i * 128 + tid;
            int row = flat >> 2, kc = (flat & 3) * 8;
            cp_async16(ska + stage * CTX_TILEB + (row * CTX_LD + kc) * 2,
                       kp + (size_t)row * L + l0 + kc);
            cp_async16(skv + stage * CTX_TILEB + (row * CTX_LD + kc) * 2,
                       vp + (size_t)row * L + l0 + kc);
        }
    };

    float acc[8][4];
#pragma unroll
    for (int ni = 0; ni < 8; ni++)
#pragma unroll
        for (int r = 0; r < 4; r++) acc[ni][r] = 0.f;

    const int ktiles = (L / NCHUNK) >> 5;
#pragma unroll
    for (int s = 0; s < 2; s++) {
        load_stage(s, s);
        cp_commit();
    }
    cp_wait<1>();
    __syncthreads();

    for (int kt = 0; kt < ktiles; kt++) {
        uint32_t abase = ska + (kt % 3) * CTX_TILEB;
        uint32_t bbase = skv + (kt % 3) * CTX_TILEB;
#pragma unroll
        for (int kk = 0; kk < 2; kk++) {
            const int kbh = kk * 16;
            uint32_t af[4], bf[8][2];
            {
                int row = warp * 16 + r8 + (t8 & 1) * 8;
                int col = kbh + (t8 >> 1) * 8;
                ldsm_x4(af, abase + (row * CTX_LD + col) * 2);
            }
#pragma unroll
            for (int np = 0; np < 4; np++) {
                int row = np * 16 + r8 + (t8 >> 1) * 8;
                int col = kbh + (t8 & 1) * 8;
                uint32_t r4[4];
                ldsm_x4(r4, bbase + (row * CTX_LD + col) * 2);
                bf[np * 2][0] = r4[0]; bf[np * 2][1] = r4[1];
                bf[np * 2 + 1][0] = r4[2]; bf[np * 2 + 1][1] = r4[3];
            }
#pragma unroll
            for (int ni = 0; ni < 8; ni++)
                mma_f16(acc[ni], af, bf[ni]);
        }
        int nt = kt + 2;
        if (nt < ktiles) {
            load_stage(nt % 3, nt);
            cp_commit();
            cp_wait<1>();
        } else {
            cp_wait<0>();
        }
        __syncthreads();
    }

    float* cp = ctxp + ((size_t)chunk * BH + bh) * (DHEAD * DHEAD);
    int d = warp * 16 + gid;
#pragma unroll
    for (int ni = 0; ni < 8; ni++) {
        int col = ni * 8 + t4 * 2;
        *(float2*)&cp[d * DHEAD + col] = make_float2(acc[ni][0], acc[ni][1]);
        *(float2*)&cp[(d + 8) * DHEAD + col] = make_float2(acc[ni][2], acc[ni][3]);
    }
}

// ---------------------------------------------------------------------------
// Reduce chunks + divide by ksum, emit ctxh fp16 transposed [bh][e][d]
// ---------------------------------------------------------------------------
__global__ void ctx_reduce_kernel(const float* __restrict__ ctxp,
                                  const float* __restrict__ ksum,
                                  __half* __restrict__ ctxh) {
    int i = blockIdx.x * 256 + threadIdx.x; // over BH*4096
    int bh = i >> 12;
    int rem = i & 4095;
    int d = rem >> 6, e = rem & 63;
    float s = 0.f;
#pragma unroll
    for (int c = 0; c < NCHUNK; c++)
        s += ctxp[(size_t)c * (BH * DHEAD * DHEAD) + i];
    int b = bh >> 3, h = bh & 7;
    float kv = ksum[(size_t)b * HIDDEN + h * DHEAD + d];
    ctxh[((size_t)bh << 12) + e * DHEAD + d] = __float2half(s / kv);
}

// ---------------------------------------------------------------------------
// Mega out-kernel: phase 0 computes attn B-tile in smem (per head HMMA),
// phase 1 = out-GEMM (A=wouth staged, B resident) + bias + RMSNorm + residual.
// CTA: 64 l's, full M=512. 512 threads (16 warps).
// smem: region0 = EQ(8x64x72) + CH(8x64x72) halves [phase0] reused as
//       A 3-stage ring [phase1]; Bs resident 64x520 halves.
// ---------------------------------------------------------------------------
#define EQ_LD 72
#define EQ_BYTES (8 * 64 * EQ_LD * 2)    // 73728
#define REGION0 (2 * EQ_BYTES)           // 147456 (>= 3*40960 A stages)
#define OA_BYTES (512 * H_LD * 2)        // 40960 per A stage
#define BS_LD 520
#define BS_BYTES (64 * BS_LD * 2)        // 66560
#define OUT_SMEM (REGION0 + BS_BYTES)    // 214016

__global__ __launch_bounds__(512) void gemm_out_mega(
    const __half* __restrict__ wouth, const __half* __restrict__ expqT,
    const float* __restrict__ qsum, const __half* __restrict__ ctxh,
    const float* __restrict__ bias, const float* __restrict__ gout,
    const float* __restrict__ x, float* __restrict__ out) {
    __shared__ float colsum[64];
    __shared__ float qs_s[8][64];
    uint32_t sbase = (uint32_t)__cvta_generic_to_shared(sgm_h);
    uint32_t eq = sbase;                 // EQ  [h][l][d] stride EQ_LD
    uint32_t ch = sbase + EQ_BYTES;      // CH  [h][e][d] stride EQ_LD
    uint32_t bs = sbase + REGION0;       // Bs  [l][e512] stride BS_LD

    const int tid = threadIdx.x;
    const int lane = tid & 31;
    const int warp = tid >> 5;
    const int gid = lane >> 2;
    const int t4 = lane & 3;
    const int t8 = lane >> 3;
    const int r8 = lane & 7;
    const int bz = blockIdx.y;
    const int l0 = blockIdx.x * 64;

    // ---- phase 0: load expq tiles + ctxh + qsum ----
#pragma unroll
    for (int i = 0; i < 8; i++) {
        int flat = i * 512 + tid;            // 4096 cp16: [h][row][seg]
        int h = flat >> 9, row = (flat >> 3) & 63, seg = flat & 7;
        const __half* qp = expqT + (((size_t)bz * HEADS + h) * L + l0 + row) * DHEAD;
        cp_async16(eq + (h * 64 * EQ_LD + row * EQ_LD + seg * 8) * 2, qp + seg * 8);
        const __half* cpp = ctxh + (((size_t)bz * HEADS + h) << 12) + (size_t)row * DHEAD;
        cp_async16(ch + (h * 64 * EQ_LD + row * EQ_LD + seg * 8) * 2, cpp + seg * 8);
    }
    if (tid < 128) {
        int h = tid >> 4, seg = tid & 15;    // 16 floats per seg*4
        const float* qp = qsum + ((size_t)bz * HEADS + h) * L + l0 + seg * 4;
        cp_async16((uint32_t)__cvta_generic_to_shared(&qs_s[h][seg * 4]), qp);
    }
    cp_commit();
    cp_wait<0>();
    __syncthreads();

    // ---- phase 0 compute: warp w -> head h = w>>1, l-half sub = w&1 ----
    {
        const int h = warp >> 1;
        const int sub = warp & 1;
        uint32_t eqh = eq + (h * 64 * EQ_LD) * 2;
        uint32_t chh = ch + (h * 64 * EQ_LD) * 2;
        float pacc[2][8][4];
#pragma unroll
        for (int mi = 0; mi < 2; mi++)
#pragma unroll
            for (int ni = 0; ni < 8; ni++)
#pragma unroll
                for (int r = 0; r < 4; r++) pacc[mi][ni][r] = 0.f;

#pragma unroll
        for (int kt = 0; kt < 4; kt++) {
            const int kbh = kt * 16;
            uint32_t af[2][4], bf[8][2];
#pragma unroll
            for (int mi = 0; mi < 2; mi++) {
                int row = sub * 32 + mi * 16 + r8 + (t8 & 1) * 8;
                int col = kbh + (t8 >> 1) * 8;
                ldsm_x4(af[mi], eqh + (row * EQ_LD + col) * 2);
            }
#pragma unroll
            for (int np = 0; np < 4; np++) {
                int row = np * 16 + r8 + (t8 >> 1) * 8;
                int col = kbh + (t8 & 1) * 8;
                uint32_t r4[4];
                ldsm_x4(r4, chh + (row * EQ_LD + col) * 2);
                bf[np * 2][0] = r4[0]; bf[np * 2][1] = r4[1];
                bf[np * 2 + 1][0] = r4[2]; bf[np * 2 + 1][1] = r4[3];
            }
#pragma unroll
            for (int mi = 0; mi < 2; mi++)
#pragma unroll
                for (int ni = 0; ni < 8; ni++)
                    mma_f16(pacc[mi][ni], af[mi], bf[ni]);
        }
        // scale + store to Bs
#pragma unroll
        for (int mi = 0; mi < 2; mi++) {
            int r0 = sub * 32 + mi * 16 + gid;
            float inv0 = ATTN_SCALE / qs_s[h][r0];
            float inv1 = ATTN_SCALE / qs_s[h][r0 + 8];
#pragma unroll
            for (int ni = 0; ni < 8; ni++) {
                int col = h * 64 + ni * 8 + t4 * 2;
                __half* b0 = (__half*)sgm_h + REGION0 / 2 + r0 * BS_LD + col;
                __half* b1 = (__half*)sgm_h + REGION0 / 2 + (r0 + 8) * BS_LD + col;
                *(__half2*)b0 = __floats2half2_rn(pacc[mi][ni][0] * inv0,
                                                  pacc[mi][ni][1] * inv0);
                *(__half2*)b1 = __floats2half2_rn(pacc[mi][ni][2] * inv1,
                                                  pacc[mi][ni][3] * inv1);
            }
        }
    }
    __syncthreads();

    // ---- phase 1: out-GEMM with A staged (3-ring in region0), B resident ----
    float acc[2][8][4];
#pragma unroll
    for (int mi = 0; mi < 2; mi++)
#pragma unroll
        for (int ni = 0; ni < 8; ni++)
#pragma unroll
            for (int r = 0; r < 4; r++) acc[mi][ni][r] = 0.f;

    auto load_stage = [&](int kt) {
        uint32_t sA = sbase + (kt % 3) * OA_BYTES;
        int k0 = kt * 32;
#pragma unroll
        for (int i = 0; i < 4; i++) {
            int c = tid + i * 512;
            int row = c >> 2, kc = (c & 3) * 8;
            cp_async16(sA + (row * H_LD + kc) * 2,
                       wouth + (size_t)row * HIDDEN + k0 + kc);
        }
    };

    const int ktiles = HIDDEN >> 5;
#pragma unroll
    for (int s = 0; s < 2; s++) {
        load_stage(s);
        cp_commit();
    }
    cp_wait<1>();
    __syncthreads();

    for (int kt = 0; kt < ktiles; kt++) {
        uint32_t abase = sbase + (kt % 3) * OA_BYTES;
#pragma unroll
        for (int kk = 0; kk < 2; kk++) {
            const int kbh = kk * 16;
            uint32_t af[2][4], bf[8][2];
#pragma unroll
            for (int mi = 0; mi < 2; mi++) {
                int row = warp * 32 + mi * 16 + r8 + (t8 & 1) * 8;
                int col = kbh + (t8 >> 1) * 8;
                ldsm_x4(af[mi], abase + (row * H_LD + col) * 2);
            }
#pragma unroll
            for (int np = 0; np < 4; np++) {
                int row = np * 16 + r8 + (t8 >> 1) * 8;
                int col = kt * 32 + kbh + (t8 & 1) * 8;
                uint32_t r4[4];
                ldsm_x4(r4, bs + (row * BS_LD + col) * 2);
                bf[np * 2][0] = r4[0]; bf[np * 2][1] = r4[1];
                bf[np * 2 + 1][0] = r4[2]; bf[np * 2 + 1][1] = r4[3];
            }
#pragma unroll
            for (int mi = 0; mi < 2; mi++)
#pragma unroll
                for (int ni = 0; ni < 8; ni++)
                    mma_f16(acc[mi][ni], af[mi], bf[ni]);
        }
        int nt = kt + 2;
        if (nt < ktiles) {
            load_stage(nt);
            cp_commit();
            cp_wait<1>();
        } else {
            cp_wait<0>();
        }
        __syncthreads();
    }

    // ---- fused epilogue: bias + per-column rmsnorm + residual ----
    float bvs[2][2];
#pragma unroll
    for (int mi = 0; mi < 2; mi++) {
        int r0 = warp * 32 + mi * 16 + gid;
        bvs[mi][0] = bias[r0];
        bvs[mi][1] = bias[r0 + 8];
    }
    if (tid < 64) colsum[tid] = 0.f;
    __syncthreads();

#pragma unroll
    for (int ni = 0; ni < 8; ni++) {
#pragma unroll
        for (int c01 = 0; c01 < 2; c01++) {
            float part = 0.f;
#pragma unroll
            for (int mi = 0; mi < 2; mi++) {
                float v0 = acc[mi][ni][c01] + bvs[mi][0];
                float v1 = acc[mi][ni][2 + c01] + bvs[mi][1];
                acc[mi][ni][c01] = v0;
                acc[mi][ni][2 + c01] = v1;
                part += v0 * v0 + v1 * v1;
            }
            part += __shfl_xor_sync(0xFFFFFFFFu, part, 4);
            part += __shfl_xor_sync(0xFFFFFFFFu, part, 8);
            part += __shfl_xor_sync(0xFFFFFFFFu, part, 16);
            if (gid == 0) atomicAdd(&colsum[ni * 8 + t4 * 2 + c01], part);
        }
    }
    __syncthreads();

    float scl[8][2];
#pragma unroll
    for (int ni = 0; ni < 8; ni++) {
        int col = ni * 8 + t4 * 2;
        scl[ni][0] = SQRT_C / fmaxf(sqrtf(colsum[col]), 1e-12f);
        scl[ni][1] = SQRT_C / fmaxf(sqrtf(colsum[col + 1]), 1e-12f);
    }

#pragma unroll
    for (int mi = 0; mi < 2; mi++) {
        int r0 = warp * 32 + mi * 16 + gid;
        float g0 = gout[r0], g1 = gout[r0 + 8];
        const float* xr0 = x + ((size_t)bz * C + r0) * L + l0;
        const float* xr1 = x + ((size_t)bz * C + r0 + 8) * L + l0;
        float* or0 = out + ((size_t)bz * C + r0) * L + l0;
        float* or1 = out + ((size_t)bz * C + r0 + 8) * L + l0;
#pragma unroll
        for (int ni = 0; ni < 8; ni++) {
            int col = ni * 8 + t4 * 2;
            float2 xv0 = *(const float2*)&xr0[col];
            float2 xv1 = *(const float2*)&xr1[col];
            float2 v0 = make_float2(acc[mi][ni][0] * scl[ni][0] * g0 + xv0.x,
                                    acc[mi][ni][1] * scl[ni][1] * g0 + xv0.y);
            float2 v1 = make_float2(acc[mi][ni][2] * scl[ni][0] * g1 + xv1.x,
                                    acc[mi][ni][3] * scl[ni][1] * g1 + xv1.y);
            *(float2*)&or0[col] = v0;
            *(float2*)&or1[col] = v1;
        }
    }
}

// ---------------------------------------------------------------------------
extern "C" void kernel_launch(void* const* d_in, const int* in_sizes, int n_in,
                              void* d_out, int out_size) {
    const float* x     = (const float*)d_in[0];
    const float* g_in  = (const float*)d_in[1];
    const float* w_qkv = (const float*)d_in[2];
    const float* w_out = (const float*)d_in[3];
    const float* b_out = (const float*)d_in[4];
    const float* g_out = (const float*)d_in[5];
    float* out = (float*)d_out;

    __half *w2h, *wouth, *xhT, *qkvh, *expqT, *ctxh;
    float *qsum, *ksum, *ctxp;
    cudaGetSymbolAddress((void**)&w2h, g_w2h);
    cudaGetSymbolAddress((void**)&wouth, g_wouth);
    cudaGetSymbolAddress((void**)&xhT, g_xhT);
    cudaGetSymbolAddress((void**)&qkvh, g_qkvh);
    cudaGetSymbolAddress((void**)&expqT, g_expqT);
    cudaGetSymbolAddress((void**)&qsum, g_qsum);
    cudaGetSymbolAddress((void**)&ksum, g_ksum);
    cudaGetSymbolAddress((void**)&ctxp, g_ctxp);
    cudaGetSymbolAddress((void**)&ctxh, g_ctxh);

    cudaFuncSetAttribute(gemm_qkv, cudaFuncAttributeMaxDynamicSharedMemorySize,
                         GEMM_SMEM);
    cudaFuncSetAttribute(gemm_out_mega, cudaFuncAttributeMaxDynamicSharedMemorySize,
                         OUT_SMEM);

    // 0. merged prologue: weight conversions + ksum zero
    prologue_kernel<<<(QKV_CH * C) / 256, 256>>>(w_qkv, g_in, w_out,
                                                 w2h, wouth, ksum);

    // 1. fused rmsnorm scale + transpose -> xhT fp16
    normxpose_kernel<<<dim3(L / 32, B), 256>>>(x, xhT);

    // 2. qkv GEMM (fp32 accum) with fused exp epilogues
    gemm_qkv<<<dim3(L / 128, QKV_CH / 128, B), 256, GEMM_SMEM>>>(
        w2h, xhT, qkvh, expqT, qsum, ksum, C, L,
        (size_t)L * C, (size_t)QKV_CH * L);

    // 3. context partials via HMMA, reduce + /ksum -> ctxh
    ctx_part_mma<<<dim3(BH, NCHUNK), 128>>>(qkvh, ctxp);
    ctx_reduce_kernel<<<(BH * DHEAD * DHEAD) / 256, 256>>>(ctxp, ksum, ctxh);

    // 4. mega out-kernel: attn (phase 0) + out-GEMM + RMSNorm + residual
    gemm_out_mega<<<dim3(L / 64, B), 512, OUT_SMEM>>>(
        wouth, expqT, qsum, ctxh, b_out, g_out, x, out);
}

// round 15
// speedup vs baseline: 1.3226x; 1.0146x over previous
#include <cuda_runtime.h>
#include <cuda_fp16.h>
#include <math.h>
#include <stdint.h>

// Problem constants
#define B 8
#define C 512
#define L 4096
#define HEADS 8
#define DHEAD 64
#define HIDDEN 512           // HEADS*DHEAD
#define QKV_CH 1536          // 3*HIDDEN
#define SQRT_C 22.627416998f // sqrt(512)
#define ATTN_SCALE 0.125f    // 64^-0.5
#define NCHUNK 8             // ctx split factor over L
#define BH (B * HEADS)
#define BHALF 4              // batches per stream

// Scratch buffers
__device__ __half g_w2h[(size_t)QKV_CH * C];        // w_qkv * g_in, fp16
__device__ __half g_wouth[(size_t)C * HIDDEN];
__device__ __half g_xhT[(size_t)B * L * C];         // (x*s)^T fp16 [b][l][c]
__device__ __half g_qkvh[(size_t)B * QKV_CH * L];   // fp16 [b][ch][l]; k rows hold exp(k)
__device__ __half g_expqT[(size_t)BH * L * DHEAD];  // exp(q) [bh][l][d]
__device__ float  g_qsum[(size_t)BH * L];           // per-(bh,l) sum of exp(q) over d
__device__ float  g_ksum[(size_t)B * HIDDEN];       // per-(b,kch) sum of exp(k) over l
__device__ float  g_ctxp[(size_t)NCHUNK * BH * DHEAD * DHEAD];
__device__ __half g_ctxh[(size_t)BH * DHEAD * DHEAD]; // ctx^T/ksum fp16 [bh][e][d]

// ---------------------------------------------------------------------------
// PTX helpers
// ---------------------------------------------------------------------------
__device__ __forceinline__ void cp_async16(uint32_t dst, const void* src) {
    asm volatile("cp.async.cg.shared.global [%0], [%1], 16;" :: "r"(dst), "l"(src));
}
__device__ __forceinline__ void cp_commit() {
    asm volatile("cp.async.commit_group;");
}
template <int N>
__device__ __forceinline__ void cp_wait() {
    asm volatile("cp.async.wait_group %0;" :: "n"(N));
}
__device__ __forceinline__ void ldsm_x4(uint32_t r[4], uint32_t addr) {
    asm volatile("ldmatrix.sync.aligned.m8n8.x4.shared.b16 {%0,%1,%2,%3}, [%4];"
                 : "=r"(r[0]), "=r"(r[1]), "=r"(r[2]), "=r"(r[3]) : "r"(addr));
}
__device__ __forceinline__ void mma_f16(float d[4], const uint32_t a[4],
                                        const uint32_t b[2]) {
    asm volatile(
        "mma.sync.aligned.m16n8k16.row.col.f32.f16.f16.f32 "
        "{%0,%1,%2,%3}, {%4,%5,%6,%7}, {%8,%9}, {%0,%1,%2,%3};"
        : "+f"(d[0]), "+f"(d[1]), "+f"(d[2]), "+f"(d[3])
        : "r"(a[0]), "r"(a[1]), "r"(a[2]), "r"(a[3]),
          "r"(b[0]), "r"(b[1]));
}

// ---------------------------------------------------------------------------
// Merged prologue: w2h, wouth conversions + ksum zero (one launch)
// ---------------------------------------------------------------------------
__global__ void prologue_kernel(const float* __restrict__ w_qkv,
                                const float* __restrict__ g_in,
                                const float* __restrict__ w_out,
                                __half* __restrict__ w2h,
                                __half* __restrict__ wouth,
                                float* __restrict__ ksum) {
    int i = blockIdx.x * 256 + threadIdx.x;
    w2h[i] = __float2half(w_qkv[i] * g_in[i & (C - 1)]);
    if (i < C * HIDDEN) wouth[i] = __float2half(w_out[i]);
    if (i < B * HIDDEN) ksum[i] = 0.f;
}

// ---------------------------------------------------------------------------
// Fused rmsnorm-scale + transpose: xhT[b][l][c] = fp16(x[b][c][l] * s[b,l])
// ---------------------------------------------------------------------------
#define NXS 34
__global__ __launch_bounds__(256) void normxpose_kernel(const float* __restrict__ x,
                                                        __half* __restrict__ xhT,
                                                        int b_base) {
    __shared__ __half t[512 * NXS];   // t[c*NXS + l]
    __shared__ float ssred[8][32];
    __shared__ float sc[32];
    int b = blockIdx.y + b_base;
    int l0 = blockIdx.x * 32;
    int tid = threadIdx.x;
    int l = tid & 31;
    const float* xp = x + ((size_t)b * C) * L + l0;
    float ss = 0.f;
#pragma unroll
    for (int i = 0; i < 64; i++) {
        int c = i * 8 + (tid >> 5);
        float v = xp[(size_t)c * L + l];
        ss += v * v;
        t[c * NXS + l] = __float2half(v);
    }
    ssred[tid >> 5][l] = ss;
    __syncthreads();
    if (tid < 32) {
        float s = 0.f;
#pragma unroll
        for (int j = 0; j < 8; j++) s += ssred[j][tid];
        sc[tid] = SQRT_C / fmaxf(sqrtf(s), 1e-12f);
    }
    __syncthreads();
    __half* op = xhT + ((size_t)b * L + l0) * C;
#pragma unroll
    for (int i = 0; i < 64; i++) {
        int flat = i * 256 + tid;
        int lo = flat >> 9, c = flat & 511;
        op[(size_t)lo * C + c] =
            __float2half(__half2float(t[c * NXS + lo]) * sc[lo]);
    }
}

// ---------------------------------------------------------------------------
// QKV GEMM: 128x128x32, 8 warps (2x4) of 64x32, 3-stage cp.async, fp32 accum.
// ---------------------------------------------------------------------------
#define H_LD 40
#define H_TILEB (128 * H_LD * 2)
#define STAGES 3
#define GEMM_SMEM (STAGES * 2 * H_TILEB)

extern __shared__ __half sgm_h[];

__device__ __forceinline__ void qkv_load_tile(uint32_t sa, uint32_t sb, int stage,
                                              const __half* Ap, const __half* Bp,
                                              int k0, int K, int tid) {
#pragma unroll
    for (int i = 0; i < 2; i++) {
        int c = tid + i * 256;
        int row = c >> 2, kc = (c & 3) * 8;
        cp_async16(sa + stage * H_TILEB + (row * H_LD + kc) * 2,
                   Ap + (size_t)row * K + k0 + kc);
    }
#pragma unroll
    for (int i = 0; i < 2; i++) {
        int c = tid + i * 256;
        int row = c >> 2, kc = (c & 3) * 8;
        cp_async16(sb + stage * H_TILEB + (row * H_LD + kc) * 2,
                   Bp + (size_t)row * K + k0 + kc);
    }
}

__global__ __launch_bounds__(256) void gemm_qkv(
    const __half* __restrict__ A, const __half* __restrict__ Bb,
    __half* __restrict__ Cb, __half* __restrict__ expqT,
    float* __restrict__ qsum, float* __restrict__ ksum,
    int K, int ldc, size_t strideB, size_t strideC, int b_base) {
    uint32_t sa = (uint32_t)__cvta_generic_to_shared(sgm_h);
    uint32_t sb = sa + STAGES * H_TILEB;

    const int tid = threadIdx.x;
    const int lane = tid & 31;
    const int warp = tid >> 5;
    const int gid = lane >> 2;
    const int t4 = lane & 3;
    const int wm = warp >> 2;
    const int wn = warp & 3;
    const int t8 = lane >> 3;
    const int r8 = lane & 7;

    const int b = blockIdx.z + b_base;
    const __half* Ap = A + (size_t)blockIdx.y * 128 * K;
    const __half* Bp = Bb + (size_t)b * strideB + (size_t)blockIdx.x * 128 * K;
    __half* Cp = Cb + (size_t)b * strideC +
                 (size_t)blockIdx.y * 128 * ldc + (size_t)blockIdx.x * 128;

    float acc[4][4][4];
#pragma unroll
    for (int mi = 0; mi < 4; mi++)
#pragma unroll
        for (int ni = 0; ni < 4; ni++)
#pragma unroll
            for (int r = 0; r < 4; r++) acc[mi][ni][r] = 0.f;

    const int ktiles = K >> 5;
#pragma unroll
    for (int s = 0; s < STAGES - 1; s++) {
        qkv_load_tile(sa, sb, s, Ap, Bp, s * 32, K, tid);
        cp_commit();
    }
    cp_wait<STAGES - 2>();
    __syncthreads();

    for (int kt = 0; kt < ktiles; kt++) {
        uint32_t abase = sa + (kt % STAGES) * H_TILEB;
        uint32_t bbase = sb + (kt % STAGES) * H_TILEB;
#pragma unroll
        for (int kk = 0; kk < 2; kk++) {
            const int kbh = kk * 16;
            uint32_t af[4][4], bf[4][2];
#pragma unroll
            for (int mi = 0; mi < 4; mi++) {
                int row = wm * 64 + mi * 16 + r8 + (t8 & 1) * 8;
                int col = kbh + (t8 >> 1) * 8;
                ldsm_x4(af[mi], abase + (row * H_LD + col) * 2);
            }
#pragma unroll
            for (int np = 0; np < 2; np++) {
                int row = wn * 32 + np * 16 + r8 + (t8 >> 1) * 8;
                int col = kbh + (t8 & 1) * 8;
                uint32_t r4[4];
                ldsm_x4(r4, bbase + (row * H_LD + col) * 2);
                bf[np * 2][0] = r4[0]; bf[np * 2][1] = r4[1];
                bf[np * 2 + 1][0] = r4[2]; bf[np * 2 + 1][1] = r4[3];
            }
#pragma unroll
            for (int mi = 0; mi < 4; mi++)
#pragma unroll
                for (int ni = 0; ni < 4; ni++)
                    mma_f16(acc[mi][ni], af[mi], bf[ni]);
        }
        int nt = kt + STAGES - 1;
        if (nt < ktiles) {
            qkv_load_tile(sa, sb, nt % STAGES, Ap, Bp, nt * 32, K, tid);
            cp_commit();
            cp_wait<STAGES - 2>();
        } else {
            cp_wait<0>();
        }
        __syncthreads();
    }

    const int l0 = blockIdx.x * 128;
    const int region = blockIdx.y >> 2;

    if (region == 0) {
        const int h = (blockIdx.y << 1) + wm;
        __half* qtb = expqT + (((size_t)b * HEADS + h) * L + l0) * DHEAD;
        float cs0[4] = {0.f, 0.f, 0.f, 0.f};
        float cs1[4] = {0.f, 0.f, 0.f, 0.f};
#pragma unroll
        for (int mi = 0; mi < 4; mi++) {
            const int d0 = mi * 16 + gid;
#pragma unroll
            for (int ni = 0; ni < 4; ni++) {
                const int col = wn * 32 + ni * 8 + t4 * 2;
                float e0 = expf(acc[mi][ni][0]);
                float e1 = expf(acc[mi][ni][1]);
                float e2 = expf(acc[mi][ni][2]);
                float e3 = expf(acc[mi][ni][3]);
                __half* q0 = qtb + (size_t)col * DHEAD;
                __half* q1 = q0 + DHEAD;
                q0[d0] = __float2half(e0);
                q0[d0 + 8] = __float2half(e2);
                q1[d0] = __float2half(e1);
                q1[d0 + 8] = __float2half(e3);
                cs0[ni] += e0 + e2;
                cs1[ni] += e1 + e3;
            }
        }
#pragma unroll
        for (int ni = 0; ni < 4; ni++) {
            cs0[ni] += __shfl_xor_sync(0xFFFFFFFFu, cs0[ni], 4);
            cs0[ni] += __shfl_xor_sync(0xFFFFFFFFu, cs0[ni], 8);
            cs0[ni] += __shfl_xor_sync(0xFFFFFFFFu, cs0[ni], 16);
            cs1[ni] += __shfl_xor_sync(0xFFFFFFFFu, cs1[ni], 4);
            cs1[ni] += __shfl_xor_sync(0xFFFFFFFFu, cs1[ni], 8);
            cs1[ni] += __shfl_xor_sync(0xFFFFFFFFu, cs1[ni], 16);
            if (gid == 0) {
                const int col = wn * 32 + ni * 8 + t4 * 2;
                float* qs = qsum + ((size_t)b * HEADS + h) * L + l0 + col;
                qs[0] = cs0[ni];
                qs[1] = cs1[ni];
            }
        }
    } else if (region == 1) {
#pragma unroll
        for (int mi = 0; mi < 4; mi++) {
            const int r0 = wm * 64 + mi * 16 + gid;
            float rs0 = 0.f, rs1 = 0.f;
#pragma unroll
            for (int ni = 0; ni < 4; ni++) {
                const int col = wn * 32 + ni * 8 + t4 * 2;
                float e0 = expf(acc[mi][ni][0]);
                float e1 = expf(acc[mi][ni][1]);
                float e2 = expf(acc[mi][ni][2]);
                float e3 = expf(acc[mi][ni][3]);
                *(__half2*)&Cp[(size_t)r0 * ldc + col] = __floats2half2_rn(e0, e1);
                *(__half2*)&Cp[(size_t)(r0 + 8) * ldc + col] = __floats2half2_rn(e2, e3);
                rs0 += e0 + e1;
                rs1 += e2 + e3;
            }
            rs0 += __shfl_xor_sync(0xFFFFFFFFu, rs0, 1);
            rs0 += __shfl_xor_sync(0xFFFFFFFFu, rs0, 2);
            rs1 += __shfl_xor_sync(0xFFFFFFFFu, rs1, 1);
            rs1 += __shfl_xor_sync(0xFFFFFFFFu, rs1, 2);
            if (t4 == 0) {
                const int ch = (blockIdx.y - 4) * 128 + r0;
                atomicAdd(&ksum[(size_t)b * HIDDEN + ch], rs0);
                atomicAdd(&ksum[(size_t)b * HIDDEN + ch + 8], rs1);
            }
        }
    } else {
#pragma unroll
        for (int mi = 0; mi < 4; mi++) {
            const int r0 = wm * 64 + mi * 16 + gid;
#pragma unroll
            for (int ni = 0; ni < 4; ni++) {
                const int col = wn * 32 + ni * 8 + t4 * 2;
                *(__half2*)&Cp[(size_t)r0 * ldc + col] =
                    __floats2half2_rn(acc[mi][ni][0], acc[mi][ni][1]);
                *(__half2*)&Cp[(size_t)(r0 + 8) * ldc + col] =
                    __floats2half2_rn(acc[mi][ni][2], acc[mi][ni][3]);
            }
        }
    }
}

// ---------------------------------------------------------------------------
// ctx partial via HMMA (fp32 accum)
// ---------------------------------------------------------------------------
#define CTX_LD 40
#define CTX_TILEB (64 * CTX_LD * 2)

__global__ __launch_bounds__(128) void ctx_part_mma(const __half* __restrict__ qkvh,
                                                    float* __restrict__ ctxp,
                                                    int b_base) {
    __shared__ __half csk[3 * 64 * CTX_LD];
    __shared__ __half csv[3 * 64 * CTX_LD];
    uint32_t ska = (uint32_t)__cvta_generic_to_shared(csk);
    uint32_t skv = (uint32_t)__cvta_generic_to_shared(csv);

    int bh = blockIdx.x + b_base * HEADS;
    int chunk = blockIdx.y;
    int b = bh >> 3, h = bh & 7;
    const __half* kp = qkvh + ((size_t)b * QKV_CH + HIDDEN + h * DHEAD) * L;
    const __half* vp = qkvh + ((size_t)b * QKV_CH + 2 * HIDDEN + h * DHEAD) * L;
    const int lbeg = chunk * (L / NCHUNK);

    const int tid = threadIdx.x;
    const int lane = tid & 31;
    const int warp = tid >> 5;
    const int gid = lane >> 2;
    const int t4 = lane & 3;
    const int t8 = lane >> 3;
    const int r8 = lane & 7;

    auto load_stage = [&](int stage, int kt) {
        int l0 = lbeg + kt * 32;
#pragma unroll
        for (int i = 0; i < 2; i++) {
            int flat = i * 128 + tid;
            int row = flat >> 2, kc = (flat & 3) * 8;
            cp_async16(ska + stage * CTX_TILEB + (row * CTX_LD + kc) * 2,
                       kp + (size_t)row * L + l0 + kc);
            cp_async16(skv + stage * CTX_TILEB + (row * CTX_LD + kc) * 2,
                       vp + (size_t)row * L + l0 + kc);
        }
    };

    float acc[8][4];
#pragma unroll
    for (int ni = 0; ni < 8; ni++)
#pragma unroll
        for (int r = 0; r < 4; r++) acc[ni][r] = 0.f;

    const int ktiles = (L / NCHUNK) >> 5;
#pragma unroll
    for (int s = 0; s < 2; s++) {
        load_stage(s, s);
        cp_commit();
    }
    cp_wait<1>();
    __syncthreads();

    for (int kt = 0; kt < ktiles; kt++) {
        uint32_t abase = ska + (kt % 3) * CTX_TILEB;
        uint32_t bbase = skv + (kt % 3) * CTX_TILEB;
#pragma unroll
        for (int kk = 0; kk < 2; kk++) {
            const int kbh = kk * 16;
            uint32_t af[4], bf[8][2];
            {
                int row = warp * 16 + r8 + (t8 & 1) * 8;
                int col = kbh + (t8 >> 1) * 8;
                ldsm_x4(af, abase + (row * CTX_LD + col) * 2);
            }
#pragma unroll
            for (int np = 0; np < 4; np++) {
                int row = np * 16 + r8 + (t8 >> 1) * 8;
                int col = kbh + (t8 & 1) * 8;
                uint32_t r4[4];
                ldsm_x4(r4, bbase + (row * CTX_LD + col) * 2);
                bf[np * 2][0] = r4[0]; bf[np * 2][1] = r4[1];
                bf[np * 2 + 1][0] = r4[2]; bf[np * 2 + 1][1] = r4[3];
            }
#pragma unroll
            for (int ni = 0; ni < 8; ni++)
                mma_f16(acc[ni], af, bf[ni]);
        }
        int nt = kt + 2;
        if (nt < ktiles) {
            load_stage(nt % 3, nt);
            cp_commit();
            cp_wait<1>();
        } else {
            cp_wait<0>();
        }
        __syncthreads();
    }

    float* cp = ctxp + ((size_t)chunk * BH + bh) * (DHEAD * DHEAD);
    int d = warp * 16 + gid;
#pragma unroll
    for (int ni = 0; ni < 8; ni++) {
        int col = ni * 8 + t4 * 2;
        *(float2*)&cp[d * DHEAD + col] = make_float2(acc[ni][0], acc[ni][1]);
        *(float2*)&cp[(d + 8) * DHEAD + col] = make_float2(acc[ni][2], acc[ni][3]);
    }
}

// ---------------------------------------------------------------------------
// Reduce chunks + divide by ksum, emit ctxh fp16 transposed [bh][e][d]
// ---------------------------------------------------------------------------
__global__ void ctx_reduce_kernel(const float* __restrict__ ctxp,
                                  const float* __restrict__ ksum,
                                  __half* __restrict__ ctxh, int b_base) {
    int i = b_base * HEADS * DHEAD * DHEAD + blockIdx.x * 256 + threadIdx.x;
    int bh = i >> 12;
    int rem = i & 4095;
    int d = rem >> 6, e = rem & 63;
    float s = 0.f;
#pragma unroll
    for (int c = 0; c < NCHUNK; c++)
        s += ctxp[(size_t)c * (BH * DHEAD * DHEAD) + i];
    int b = bh >> 3, h = bh & 7;
    float kv = ksum[(size_t)b * HIDDEN + h * DHEAD + d];
    ctxh[((size_t)bh << 12) + e * DHEAD + d] = __float2half(s / kv);
}

// ---------------------------------------------------------------------------
// Mega out-kernel: phase 0 attn B-tile in smem, phase 1 out-GEMM + epilogue.
// ---------------------------------------------------------------------------
#define EQ_LD 72
#define EQ_BYTES (8 * 64 * EQ_LD * 2)
#define REGION0 (2 * EQ_BYTES)
#define OA_BYTES (512 * H_LD * 2)
#define BS_LD 520
#define BS_BYTES (64 * BS_LD * 2)
#define OUT_SMEM (REGION0 + BS_BYTES)

__global__ __launch_bounds__(512) void gemm_out_mega(
    const __half* __restrict__ wouth, const __half* __restrict__ expqT,
    const float* __restrict__ qsum, const __half* __restrict__ ctxh,
    const float* __restrict__ bias, const float* __restrict__ gout,
    const float* __restrict__ x, float* __restrict__ out, int b_base) {
    __shared__ float colsum[64];
    __shared__ float qs_s[8][64];
    uint32_t sbase = (uint32_t)__cvta_generic_to_shared(sgm_h);
    uint32_t eq = sbase;
    uint32_t ch = sbase + EQ_BYTES;
    uint32_t bs = sbase + REGION0;

    const int tid = threadIdx.x;
    const int lane = tid & 31;
    const int warp = tid >> 5;
    const int gid = lane >> 2;
    const int t4 = lane & 3;
    const int t8 = lane >> 3;
    const int r8 = lane & 7;
    const int bz = blockIdx.y + b_base;
    const int l0 = blockIdx.x * 64;

#pragma unroll
    for (int i = 0; i < 8; i++) {
        int flat = i * 512 + tid;
        int h = flat >> 9, row = (flat >> 3) & 63, seg = flat & 7;
        const __half* qp = expqT + (((size_t)bz * HEADS + h) * L + l0 + row) * DHEAD;
        cp_async16(eq + (h * 64 * EQ_LD + row * EQ_LD + seg * 8) * 2, qp + seg * 8);
        const __half* cpp = ctxh + (((size_t)bz * HEADS + h) << 12) + (size_t)row * DHEAD;
        cp_async16(ch + (h * 64 * EQ_LD + row * EQ_LD + seg * 8) * 2, cpp + seg * 8);
    }
    if (tid < 128) {
        int h = tid >> 4, seg = tid & 15;
        const float* qp = qsum + ((size_t)bz * HEADS + h) * L + l0 + seg * 4;
        cp_async16((uint32_t)__cvta_generic_to_shared(&qs_s[h][seg * 4]), qp);
    }
    cp_commit();
    cp_wait<0>();
    __syncthreads();

    {
        const int h = warp >> 1;
        const int sub = warp & 1;
        uint32_t eqh = eq + (h * 64 * EQ_LD) * 2;
        uint32_t chh = ch + (h * 64 * EQ_LD) * 2;
        float pacc[2][8][4];
#pragma unroll
        for (int mi = 0; mi < 2; mi++)
#pragma unroll
            for (int ni = 0; ni < 8; ni++)
#pragma unroll
                for (int r = 0; r < 4; r++) pacc[mi][ni][r] = 0.f;

#pragma unroll
        for (int kt = 0; kt < 4; kt++) {
            const int kbh = kt * 16;
            uint32_t af[2][4], bf[8][2];
#pragma unroll
            for (int mi = 0; mi < 2; mi++) {
                int row = sub * 32 + mi * 16 + r8 + (t8 & 1) * 8;
                int col = kbh + (t8 >> 1) * 8;
                ldsm_x4(af[mi], eqh + (row * EQ_LD + col) * 2);
            }
#pragma unroll
            for (int np = 0; np < 4; np++) {
                int row = np * 16 + r8 + (t8 >> 1) * 8;
                int col = kbh + (t8 & 1) * 8;
                uint32_t r4[4];
                ldsm_x4(r4, chh + (row * EQ_LD + col) * 2);
                bf[np * 2][0] = r4[0]; bf[np * 2][1] = r4[1];
                bf[np * 2 + 1][0] = r4[2]; bf[np * 2 + 1][1] = r4[3];
            }
#pragma unroll
            for (int mi = 0; mi < 2; mi++)
#pragma unroll
                for (int ni = 0; ni < 8; ni++)
                    mma_f16(pacc[mi][ni], af[mi], bf[ni]);
        }
#pragma unroll
        for (int mi = 0; mi < 2; mi++) {
            int r0 = sub * 32 + mi * 16 + gid;
            float inv0 = ATTN_SCALE / qs_s[h][r0];
            float inv1 = ATTN_SCALE / qs_s[h][r0 + 8];
#pragma unroll
            for (int ni = 0; ni < 8; ni++) {
                int col = h * 64 + ni * 8 + t4 * 2;
                __half* b0 = (__half*)sgm_h + REGION0 / 2 + r0 * BS_LD + col;
                __half* b1 = (__half*)sgm_h + REGION0 / 2 + (r0 + 8) * BS_LD + col;
                *(__half2*)b0 = __floats2half2_rn(pacc[mi][ni][0] * inv0,
                                                  pacc[mi][ni][1] * inv0);
                *(__half2*)b1 = __floats2half2_rn(pacc[mi][ni][2] * inv1,
                                                  pacc[mi][ni][3] * inv1);
            }
        }
    }
    __syncthreads();

    float acc[2][8][4];
#pragma unroll
    for (int mi = 0; mi < 2; mi++)
#pragma unroll
        for (int ni = 0; ni < 8; ni++)
#pragma unroll
            for (int r = 0; r < 4; r++) acc[mi][ni][r] = 0.f;

    auto load_stage = [&](int kt) {
        uint32_t sA = sbase + (kt % 3) * OA_BYTES;
        int k0 = kt * 32;
#pragma unroll
        for (int i = 0; i < 4; i++) {
            int c = tid + i * 512;
            int row = c >> 2, kc = (c & 3) * 8;
            cp_async16(sA + (row * H_LD + kc) * 2,
                       wouth + (size_t)row * HIDDEN + k0 + kc);
        }
    };

    const int ktiles = HIDDEN >> 5;
#pragma unroll
    for (int s = 0; s < 2; s++) {
        load_stage(s);
        cp_commit();
    }
    cp_wait<1>();
    __syncthreads();

    for (int kt = 0; kt < ktiles; kt++) {
        uint32_t abase = sbase + (kt % 3) * OA_BYTES;
#pragma unroll
        for (int kk = 0; kk < 2; kk++) {
            const int kbh = kk * 16;
            uint32_t af[2][4], bf[8][2];
#pragma unroll
            for (int mi = 0; mi < 2; mi++) {
                int row = warp * 32 + mi * 16 + r8 + (t8 & 1) * 8;
                int col = kbh + (t8 >> 1) * 8;
                ldsm_x4(af[mi], abase + (row * H_LD + col) * 2);
            }
#pragma unroll
            for (int np = 0; np < 4; np++) {
                int row = np * 16 + r8 + (t8 >> 1) * 8;
                int col = kt * 32 + kbh + (t8 & 1) * 8;
                uint32_t r4[4];
                ldsm_x4(r4, bs + (row * BS_LD + col) * 2);
                bf[np * 2][0] = r4[0]; bf[np * 2][1] = r4[1];
                bf[np * 2 + 1][0] = r4[2]; bf[np * 2 + 1][1] = r4[3];
            }
#pragma unroll
            for (int mi = 0; mi < 2; mi++)
#pragma unroll
                for (int ni = 0; ni < 8; ni++)
                    mma_f16(acc[mi][ni], af[mi], bf[ni]);
        }
        int nt = kt + 2;
        if (nt < ktiles) {
            load_stage(nt);
            cp_commit();
            cp_wait<1>();
        } else {
            cp_wait<0>();
        }
        __syncthreads();
    }

    float bvs[2][2];
#pragma unroll
    for (int mi = 0; mi < 2; mi++) {
        int r0 = warp * 32 + mi * 16 + gid;
        bvs[mi][0] = bias[r0];
        bvs[mi][1] = bias[r0 + 8];
    }
    if (tid < 64) colsum[tid] = 0.f;
    __syncthreads();

#pragma unroll
    for (int ni = 0; ni < 8; ni++) {
#pragma unroll
        for (int c01 = 0; c01 < 2; c01++) {
            float part = 0.f;
#pragma unroll
            for (int mi = 0; mi < 2; mi++) {
                float v0 = acc[mi][ni][c01] + bvs[mi][0];
                float v1 = acc[mi][ni][2 + c01] + bvs[mi][1];
                acc[mi][ni][c01] = v0;
                acc[mi][ni][2 + c01] = v1;
                part += v0 * v0 + v1 * v1;
            }
            part += __shfl_xor_sync(0xFFFFFFFFu, part, 4);
            part += __shfl_xor_sync(0xFFFFFFFFu, part, 8);
            part += __shfl_xor_sync(0xFFFFFFFFu, part, 16);
            if (gid == 0) atomicAdd(&colsum[ni * 8 + t4 * 2 + c01], part);
        }
    }
    __syncthreads();

    float scl[8][2];
#pragma unroll
    for (int ni = 0; ni < 8; ni++) {
        int col = ni * 8 + t4 * 2;
        scl[ni][0] = SQRT_C / fmaxf(sqrtf(colsum[col]), 1e-12f);
        scl[ni][1] = SQRT_C / fmaxf(sqrtf(colsum[col + 1]), 1e-12f);
    }

#pragma unroll
    for (int mi = 0; mi < 2; mi++) {
        int r0 = warp * 32 + mi * 16 + gid;
        float g0 = gout[r0], g1 = gout[r0 + 8];
        const float* xr0 = x + ((size_t)bz * C + r0) * L + l0;
        const float* xr1 = x + ((size_t)bz * C + r0 + 8) * L + l0;
        float* or0 = out + ((size_t)bz * C + r0) * L + l0;
        float* or1 = out + ((size_t)bz * C + r0 + 8) * L + l0;
#pragma unroll
        for (int ni = 0; ni < 8; ni++) {
            int col = ni * 8 + t4 * 2;
            float2 xv0 = *(const float2*)&xr0[col];
            float2 xv1 = *(const float2*)&xr1[col];
            float2 v0 = make_float2(acc[mi][ni][0] * scl[ni][0] * g0 + xv0.x,
                                    acc[mi][ni][1] * scl[ni][1] * g0 + xv0.y);
            float2 v1 = make_float2(acc[mi][ni][2] * scl[ni][0] * g1 + xv1.x,
                                    acc[mi][ni][3] * scl[ni][1] * g1 + xv1.y);
            *(float2*)&or0[col] = v0;
            *(float2*)&or1[col] = v1;
        }
    }
}

// ---------------------------------------------------------------------------
extern "C" void kernel_launch(void* const* d_in, const int* in_sizes, int n_in,
                              void* d_out, int out_size) {
    const float* x     = (const float*)d_in[0];
    const float* g_in  = (const float*)d_in[1];
    const float* w_qkv = (const float*)d_in[2];
    const float* w_out = (const float*)d_in[3];
    const float* b_out = (const float*)d_in[4];
    const float* g_out = (const float*)d_in[5];
    float* out = (float*)d_out;

    __half *w2h, *wouth, *xhT, *qkvh, *expqT, *ctxh;
    float *qsum, *ksum, *ctxp;
    cudaGetSymbolAddress((void**)&w2h, g_w2h);
    cudaGetSymbolAddress((void**)&wouth, g_wouth);
    cudaGetSymbolAddress((void**)&xhT, g_xhT);
    cudaGetSymbolAddress((void**)&qkvh, g_qkvh);
    cudaGetSymbolAddress((void**)&expqT, g_expqT);
    cudaGetSymbolAddress((void**)&qsum, g_qsum);
    cudaGetSymbolAddress((void**)&ksum, g_ksum);
    cudaGetSymbolAddress((void**)&ctxp, g_ctxp);
    cudaGetSymbolAddress((void**)&ctxh, g_ctxh);

    cudaFuncSetAttribute(gemm_qkv, cudaFuncAttributeMaxDynamicSharedMemorySize,
                         GEMM_SMEM);
    cudaFuncSetAttribute(gemm_out_mega, cudaFuncAttributeMaxDynamicSharedMemorySize,
                         OUT_SMEM);

    // Fork/join two-stream batch pipeline (capture-safe event pattern).
    cudaStream_t s2;
    cudaStreamCreateWithFlags(&s2, cudaStreamNonBlocking);
    cudaEvent_t eRoot, ePro, eDone;
    cudaEventCreateWithFlags(&eRoot, cudaEventDisableTiming);
    cudaEventCreateWithFlags(&ePro, cudaEventDisableTiming);
    cudaEventCreateWithFlags(&eDone, cudaEventDisableTiming);

    cudaEventRecord(eRoot, 0);
    cudaStreamWaitEvent(s2, eRoot, 0);

    // stream 0: prologue (shared weights) then batches 0-3
    prologue_kernel<<<(QKV_CH * C) / 256, 256>>>(w_qkv, g_in, w_out,
                                                 w2h, wouth, ksum);
    cudaEventRecord(ePro, 0);

    // stream s2: batches 4-7 (normxpose independent of prologue)
    normxpose_kernel<<<dim3(L / 32, BHALF), 256, 0, s2>>>(x, xhT, BHALF);
    cudaStreamWaitEvent(s2, ePro, 0);

    normxpose_kernel<<<dim3(L / 32, BHALF), 256>>>(x, xhT, 0);

    gemm_qkv<<<dim3(L / 128, QKV_CH / 128, BHALF), 256, GEMM_SMEM>>>(
        w2h, xhT, qkvh, expqT, qsum, ksum, C, L,
        (size_t)L * C, (size_t)QKV_CH * L, 0);
    gemm_qkv<<<dim3(L / 128, QKV_CH / 128, BHALF), 256, GEMM_SMEM, s2>>>(
        w2h, xhT, qkvh, expqT, qsum, ksum, C, L,
        (size_t)L * C, (size_t)QKV_CH * L, BHALF);

    ctx_part_mma<<<dim3(BHALF * HEADS, NCHUNK), 128>>>(qkvh, ctxp, 0);
    ctx_part_mma<<<dim3(BHALF * HEADS, NCHUNK), 128, 0, s2>>>(qkvh, ctxp, BHALF);

    ctx_reduce_kernel<<<(BHALF * HEADS * DHEAD * DHEAD) / 256, 256>>>(
        ctxp, ksum, ctxh, 0);
    ctx_reduce_kernel<<<(BHALF * HEADS * DHEAD * DHEAD) / 256, 256, 0, s2>>>(
        ctxp, ksum, ctxh, BHALF);

    gemm_out_mega<<<dim3(L / 64, BHALF), 512, OUT_SMEM>>>(
        wouth, expqT, qsum, ctxh, b_out, g_out, x, out, 0);
    gemm_out_mega<<<dim3(L / 64, BHALF), 512, OUT_SMEM, s2>>>(
        wouth, expqT, qsum, ctxh, b_out, g_out, x, out, BHALF);

    cudaEventRecord(eDone, s2);
    cudaStreamWaitEvent(0, eDone, 0);
    // Streams/events intentionally not destroyed: destroying capture-forked
    // streams before capture end is illegal; kernel_launch is called O(1) times.
}

// round 17
// speedup vs baseline: 1.3510x; 1.0215x over previous
#include <cuda_runtime.h>
#include <cuda_fp16.h>
#include <math.h>
#include <stdint.h>

// Problem constants
#define B 8
#define C 512
#define L 4096
#define HEADS 8
#define DHEAD 64
#define HIDDEN 512           // HEADS*DHEAD
#define QKV_CH 1536          // 3*HIDDEN
#define SQRT_C 22.627416998f // sqrt(512)
#define ATTN_SCALE 0.125f    // 64^-0.5
#define NCHUNK 16            // ctx split factor over L
#define BH (B * HEADS)
#define BHALF 4              // batches per stream

// Scratch buffers
__device__ __half g_w2h[(size_t)QKV_CH * C];        // w_qkv * g_in, fp16
__device__ __half g_wouth[(size_t)C * HIDDEN];
__device__ __half g_xhT[(size_t)B * L * C];         // (x*s)^T fp16 [b][l][c]
__device__ __half g_qkvh[(size_t)B * QKV_CH * L];   // fp16 [b][ch][l]; k rows hold exp(k)
__device__ __half g_expqT[(size_t)BH * L * DHEAD];  // exp(q) [bh][l][d]
__device__ float  g_qsum[(size_t)BH * L];           // per-(bh,l) sum of exp(q) over d
__device__ float  g_ksum[(size_t)B * HIDDEN];       // per-(b,kch) sum of exp(k) over l
__device__ float  g_ctxp[(size_t)NCHUNK * BH * DHEAD * DHEAD];
__device__ __half g_ctxh[(size_t)BH * DHEAD * DHEAD]; // ctx^T/ksum fp16 [bh][e][d]

// ---------------------------------------------------------------------------
// PTX helpers
// ---------------------------------------------------------------------------
__device__ __forceinline__ void cp_async16(uint32_t dst, const void* src) {
    asm volatile("cp.async.cg.shared.global [%0], [%1], 16;" :: "r"(dst), "l"(src));
}
__device__ __forceinline__ void cp_commit() {
    asm volatile("cp.async.commit_group;");
}
template <int N>
__device__ __forceinline__ void cp_wait() {
    asm volatile("cp.async.wait_group %0;" :: "n"(N));
}
__device__ __forceinline__ void ldsm_x4(uint32_t r[4], uint32_t addr) {
    asm volatile("ldmatrix.sync.aligned.m8n8.x4.shared.b16 {%0,%1,%2,%3}, [%4];"
                 : "=r"(r[0]), "=r"(r[1]), "=r"(r[2]), "=r"(r[3]) : "r"(addr));
}
__device__ __forceinline__ void mma_f16(float d[4], const uint32_t a[4],
                                        const uint32_t b[2]) {
    asm volatile(
        "mma.sync.aligned.m16n8k16.row.col.f32.f16.f16.f32 "
        "{%0,%1,%2,%3}, {%4,%5,%6,%7}, {%8,%9}, {%0,%1,%2,%3};"
        : "+f"(d[0]), "+f"(d[1]), "+f"(d[2]), "+f"(d[3])
        : "r"(a[0]), "r"(a[1]), "r"(a[2]), "r"(a[3]),
          "r"(b[0]), "r"(b[1]));
}

// ---------------------------------------------------------------------------
// Merged prologue: w2h, wouth conversions + ksum zero (one launch)
// ---------------------------------------------------------------------------
__global__ void prologue_kernel(const float* __restrict__ w_qkv,
                                const float* __restrict__ g_in,
                                const float* __restrict__ w_out,
                                __half* __restrict__ w2h,
                                __half* __restrict__ wouth,
                                float* __restrict__ ksum) {
    int i = blockIdx.x * 256 + threadIdx.x;
    w2h[i] = __float2half(w_qkv[i] * g_in[i & (C - 1)]);
    if (i < C * HIDDEN) wouth[i] = __float2half(w_out[i]);
    if (i < B * HIDDEN) ksum[i] = 0.f;
}

// ---------------------------------------------------------------------------
// Fused rmsnorm-scale + transpose
// ---------------------------------------------------------------------------
#define NXS 34
__global__ __launch_bounds__(256) void normxpose_kernel(const float* __restrict__ x,
                                                        __half* __restrict__ xhT,
                                                        int b_base) {
    __shared__ __half t[512 * NXS];
    __shared__ float ssred[8][32];
    __shared__ float sc[32];
    int b = blockIdx.y + b_base;
    int l0 = blockIdx.x * 32;
    int tid = threadIdx.x;
    int l = tid & 31;
    const float* xp = x + ((size_t)b * C) * L + l0;
    float ss = 0.f;
#pragma unroll
    for (int i = 0; i < 64; i++) {
        int c = i * 8 + (tid >> 5);
        float v = xp[(size_t)c * L + l];
        ss += v * v;
        t[c * NXS + l] = __float2half(v);
    }
    ssred[tid >> 5][l] = ss;
    __syncthreads();
    if (tid < 32) {
        float s = 0.f;
#pragma unroll
        for (int j = 0; j < 8; j++) s += ssred[j][tid];
        sc[tid] = SQRT_C / fmaxf(sqrtf(s), 1e-12f);
    }
    __syncthreads();
    __half* op = xhT + ((size_t)b * L + l0) * C;
#pragma unroll
    for (int i = 0; i < 64; i++) {
        int flat = i * 256 + tid;
        int lo = flat >> 9, c = flat & 511;
        op[(size_t)lo * C + c] =
            __float2half(__half2float(t[c * NXS + lo]) * sc[lo]);
    }
}

// ---------------------------------------------------------------------------
// QKV GEMM: 128x128x32, 8 warps (2x4) of 64x32, 3-stage cp.async, fp32 accum.
// q epilogue stages through smem (QT_LD=72: 144B rows, 16B-aligned).
// ---------------------------------------------------------------------------
#define H_LD 40
#define H_TILEB (128 * H_LD * 2)
#define STAGES 3
#define GEMM_SMEM (STAGES * 2 * H_TILEB)
#define QT_LD 72   // q staging row stride (halfs); 144B rows keep uint4 aligned

extern __shared__ __half sgm_h[];

__device__ __forceinline__ void qkv_load_tile(uint32_t sa, uint32_t sb, int stage,
                                              const __half* Ap, const __half* Bp,
                                              int k0, int K, int tid) {
#pragma unroll
    for (int i = 0; i < 2; i++) {
        int c = tid + i * 256;
        int row = c >> 2, kc = (c & 3) * 8;
        cp_async16(sa + stage * H_TILEB + (row * H_LD + kc) * 2,
                   Ap + (size_t)row * K + k0 + kc);
    }
#pragma unroll
    for (int i = 0; i < 2; i++) {
        int c = tid + i * 256;
        int row = c >> 2, kc = (c & 3) * 8;
        cp_async16(sb + stage * H_TILEB + (row * H_LD + kc) * 2,
                   Bp + (size_t)row * K + k0 + kc);
    }
}

__global__ __launch_bounds__(256) void gemm_qkv(
    const __half* __restrict__ A, const __half* __restrict__ Bb,
    __half* __restrict__ Cb, __half* __restrict__ expqT,
    float* __restrict__ qsum, float* __restrict__ ksum,
    int K, int ldc, size_t strideB, size_t strideC, int b_base) {
    uint32_t sa = (uint32_t)__cvta_generic_to_shared(sgm_h);
    uint32_t sb = sa + STAGES * H_TILEB;

    const int tid = threadIdx.x;
    const int lane = tid & 31;
    const int warp = tid >> 5;
    const int gid = lane >> 2;
    const int t4 = lane & 3;
    const int wm = warp >> 2;
    const int wn = warp & 3;
    const int t8 = lane >> 3;
    const int r8 = lane & 7;

    const int b = blockIdx.z + b_base;
    const __half* Ap = A + (size_t)blockIdx.y * 128 * K;
    const __half* Bp = Bb + (size_t)b * strideB + (size_t)blockIdx.x * 128 * K;
    __half* Cp = Cb + (size_t)b * strideC +
                 (size_t)blockIdx.y * 128 * ldc + (size_t)blockIdx.x * 128;

    float acc[4][4][4];
#pragma unroll
    for (int mi = 0; mi < 4; mi++)
#pragma unroll
        for (int ni = 0; ni < 4; ni++)
#pragma unroll
            for (int r = 0; r < 4; r++) acc[mi][ni][r] = 0.f;

    const int ktiles = K >> 5;
#pragma unroll
    for (int s = 0; s < STAGES - 1; s++) {
        qkv_load_tile(sa, sb, s, Ap, Bp, s * 32, K, tid);
        cp_commit();
    }
    cp_wait<STAGES - 2>();
    __syncthreads();

    for (int kt = 0; kt < ktiles; kt++) {
        uint32_t abase = sa + (kt % STAGES) * H_TILEB;
        uint32_t bbase = sb + (kt % STAGES) * H_TILEB;
#pragma unroll
        for (int kk = 0; kk < 2; kk++) {
            const int kbh = kk * 16;
            uint32_t af[4][4], bf[4][2];
#pragma unroll
            for (int mi = 0; mi < 4; mi++) {
                int row = wm * 64 + mi * 16 + r8 + (t8 & 1) * 8;
                int col = kbh + (t8 >> 1) * 8;
                ldsm_x4(af[mi], abase + (row * H_LD + col) * 2);
            }
#pragma unroll
            for (int np = 0; np < 2; np++) {
                int row = wn * 32 + np * 16 + r8 + (t8 >> 1) * 8;
                int col = kbh + (t8 & 1) * 8;
                uint32_t r4[4];
                ldsm_x4(r4, bbase + (row * H_LD + col) * 2);
                bf[np * 2][0] = r4[0]; bf[np * 2][1] = r4[1];
                bf[np * 2 + 1][0] = r4[2]; bf[np * 2 + 1][1] = r4[3];
            }
#pragma unroll
            for (int mi = 0; mi < 4; mi++)
#pragma unroll
                for (int ni = 0; ni < 4; ni++)
                    mma_f16(acc[mi][ni], af[mi], bf[ni]);
        }
        int nt = kt + STAGES - 1;
        if (nt < ktiles) {
            qkv_load_tile(sa, sb, nt % STAGES, Ap, Bp, nt * 32, K, tid);
            cp_commit();
            cp_wait<STAGES - 2>();
        } else {
            cp_wait<0>();
        }
        __syncthreads();
    }

    const int l0 = blockIdx.x * 128;
    const int region = blockIdx.y >> 2;

    if (region == 0) {
        // --- q: exp -> smem stage [2 heads][128 l][QT_LD d] -> coalesced out ---
        __half* qt = sgm_h;      // reuse stage ring: 2*128*QT_LD halfs = 36864 B
        float cs0[4] = {0.f, 0.f, 0.f, 0.f};
        float cs1[4] = {0.f, 0.f, 0.f, 0.f};
        __syncthreads();         // mainloop smem reads done
#pragma unroll
        for (int mi = 0; mi < 4; mi++) {
            const int d0 = mi * 16 + gid;
#pragma unroll
            for (int ni = 0; ni < 4; ni++) {
                const int col = wn * 32 + ni * 8 + t4 * 2;
                float e0 = expf(acc[mi][ni][0]);
                float e1 = expf(acc[mi][ni][1]);
                float e2 = expf(acc[mi][ni][2]);
                float e3 = expf(acc[mi][ni][3]);
                __half* q0 = qt + (wm * 128 + col) * QT_LD;
                __half* q1 = q0 + QT_LD;
                q0[d0] = __float2half(e0);
                q0[d0 + 8] = __float2half(e2);
                q1[d0] = __float2half(e1);
                q1[d0 + 8] = __float2half(e3);
                cs0[ni] += e0 + e2;
                cs1[ni] += e1 + e3;
            }
        }
#pragma unroll
        for (int ni = 0; ni < 4; ni++) {
            cs0[ni] += __shfl_xor_sync(0xFFFFFFFFu, cs0[ni], 4);
            cs0[ni] += __shfl_xor_sync(0xFFFFFFFFu, cs0[ni], 8);
            cs0[ni] += __shfl_xor_sync(0xFFFFFFFFu, cs0[ni], 16);
            cs1[ni] += __shfl_xor_sync(0xFFFFFFFFu, cs1[ni], 4);
            cs1[ni] += __shfl_xor_sync(0xFFFFFFFFu, cs1[ni], 8);
            cs1[ni] += __shfl_xor_sync(0xFFFFFFFFu, cs1[ni], 16);
            if (gid == 0) {
                const int h = (blockIdx.y << 1) + wm;
                const int col = wn * 32 + ni * 8 + t4 * 2;
                float* qs = qsum + ((size_t)b * HEADS + h) * L + l0 + col;
                qs[0] = cs0[ni];
                qs[1] = cs1[ni];
            }
        }
        __syncthreads();
        // coalesced copy-out: 2 heads x 128 l x 8 segs of 8 halfs (16B chunks)
#pragma unroll
        for (int i = 0; i < 8; i++) {
            int flat = i * 256 + tid;          // 0..2047
            int hh = flat >> 10;
            int rem = flat & 1023;
            int ll = rem >> 3, seg = rem & 7;
            const int h = (blockIdx.y << 1) + hh;
            uint4 v = *(const uint4*)(qt + (hh * 128 + ll) * QT_LD + seg * 8);
            *(uint4*)(expqT + (((size_t)b * HEADS + h) * L + l0 + ll) * DHEAD +
                      seg * 8) = v;
        }
    } else if (region == 1) {
        // --- k: exp in place + per-row sums (atomic) ---
#pragma unroll
        for (int mi = 0; mi < 4; mi++) {
            const int r0 = wm * 64 + mi * 16 + gid;
            float rs0 = 0.f, rs1 = 0.f;
#pragma unroll
            for (int ni = 0; ni < 4; ni++) {
                const int col = wn * 32 + ni * 8 + t4 * 2;
                float e0 = expf(acc[mi][ni][0]);
                float e1 = expf(acc[mi][ni][1]);
                float e2 = expf(acc[mi][ni][2]);
                float e3 = expf(acc[mi][ni][3]);
                *(__half2*)&Cp[(size_t)r0 * ldc + col] = __floats2half2_rn(e0, e1);
                *(__half2*)&Cp[(size_t)(r0 + 8) * ldc + col] = __floats2half2_rn(e2, e3);
                rs0 += e0 + e1;
                rs1 += e2 + e3;
            }
            rs0 += __shfl_xor_sync(0xFFFFFFFFu, rs0, 1);
            rs0 += __shfl_xor_sync(0xFFFFFFFFu, rs0, 2);
            rs1 += __shfl_xor_sync(0xFFFFFFFFu, rs1, 1);
            rs1 += __shfl_xor_sync(0xFFFFFFFFu, rs1, 2);
            if (t4 == 0) {
                const int ch = (blockIdx.y - 4) * 128 + r0;
                atomicAdd(&ksum[(size_t)b * HIDDEN + ch], rs0);
                atomicAdd(&ksum[(size_t)b * HIDDEN + ch + 8], rs1);
            }
        }
    } else {
        // --- v: plain fp16 store ---
#pragma unroll
        for (int mi = 0; mi < 4; mi++) {
            const int r0 = wm * 64 + mi * 16 + gid;
#pragma unroll
            for (int ni = 0; ni < 4; ni++) {
                const int col = wn * 32 + ni * 8 + t4 * 2;
                *(__half2*)&Cp[(size_t)r0 * ldc + col] =
                    __floats2half2_rn(acc[mi][ni][0], acc[mi][ni][1]);
                *(__half2*)&Cp[(size_t)(r0 + 8) * ldc + col] =
                    __floats2half2_rn(acc[mi][ni][2], acc[mi][ni][3]);
            }
        }
    }
}

// ---------------------------------------------------------------------------
// ctx partial via HMMA (fp32 accum), NCHUNK=16 (256-wide chunks, 8 k-tiles)
// ---------------------------------------------------------------------------
#define CTX_LD 40
#define CTX_TILEB (64 * CTX_LD * 2)

__global__ __launch_bounds__(128) void ctx_part_mma(const __half* __restrict__ qkvh,
                                                    float* __restrict__ ctxp,
                                                    int b_base) {
    __shared__ __half csk[3 * 64 * CTX_LD];
    __shared__ __half csv[3 * 64 * CTX_LD];
    uint32_t ska = (uint32_t)__cvta_generic_to_shared(csk);
    uint32_t skv = (uint32_t)__cvta_generic_to_shared(csv);

    int bh = blockIdx.x + b_base * HEADS;
    int chunk = blockIdx.y;
    int b = bh >> 3, h = bh & 7;
    const __half* kp = qkvh + ((size_t)b * QKV_CH + HIDDEN + h * DHEAD) * L;
    const __half* vp = qkvh + ((size_t)b * QKV_CH + 2 * HIDDEN + h * DHEAD) * L;
    const int lbeg = chunk * (L / NCHUNK);

    const int tid = threadIdx.x;
    const int lane = tid & 31;
    const int warp = tid >> 5;
    const int gid = lane >> 2;
    const int t4 = lane & 3;
    const int t8 = lane >> 3;
    const int r8 = lane & 7;

    auto load_stage = [&](int stage, int kt) {
        int l0 = lbeg + kt * 32;
#pragma unroll
        for (int i = 0; i < 2; i++) {
            int flat = i * 128 + tid;
            int row = flat >> 2, kc = (flat & 3) * 8;
            cp_async16(ska + stage * CTX_TILEB + (row * CTX_LD + kc) * 2,
                       kp + (size_t)row * L + l0 + kc);
            cp_async16(skv + stage * CTX_TILEB + (row * CTX_LD + kc) * 2,
                       vp + (size_t)row * L + l0 + kc);
        }
    };

    float acc[8][4];
#pragma unroll
    for (int ni = 0; ni < 8; ni++)
#pragma unroll
        for (int r = 0; r < 4; r++) acc[ni][r] = 0.f;

    const int ktiles = (L / NCHUNK) >> 5;   // 8
#pragma unroll
    for (int s = 0; s < 2; s++) {
        load_stage(s, s);
        cp_commit();
    }
    cp_wait<1>();
    __syncthreads();

    for (int kt = 0; kt < ktiles; kt++) {
        uint32_t abase = ska + (kt % 3) * CTX_TILEB;
        uint32_t bbase = skv + (kt % 3) * CTX_TILEB;
#pragma unroll
        for (int kk = 0; kk < 2; kk++) {
            const int kbh = kk * 16;
            uint32_t af[4], bf[8][2];
            {
                int row = warp * 16 + r8 + (t8 & 1) * 8;
                int col = kbh + (t8 >> 1) * 8;
                ldsm_x4(af, abase + (row * CTX_LD + col) * 2);
            }
#pragma unroll
            for (int np = 0; np < 4; np++) {
                int row = np * 16 + r8 + (t8 >> 1) * 8;
                int col = kbh + (t8 & 1) * 8;
                uint32_t r4[4];
                ldsm_x4(r4, bbase + (row * CTX_LD + col) * 2);
                bf[np * 2][0] = r4[0]; bf[np * 2][1] = r4[1];
                bf[np * 2 + 1][0] = r4[2]; bf[np * 2 + 1][1] = r4[3];
            }
#pragma unroll
            for (int ni = 0; ni < 8; ni++)
                mma_f16(acc[ni], af, bf[ni]);
        }
        int nt = kt + 2;
        if (nt < ktiles) {
            load_stage(nt % 3, nt);
            cp_commit();
            cp_wait<1>();
        } else {
            cp_wait<0>();
        }
        __syncthreads();
    }

    float* cp = ctxp + ((size_t)chunk * BH + bh) * (DHEAD * DHEAD);
    int d = warp * 16 + gid;
#pragma unroll
    for (int ni = 0; ni < 8; ni++) {
        int col = ni * 8 + t4 * 2;
        *(float2*)&cp[d * DHEAD + col] = make_float2(acc[ni][0], acc[ni][1]);
        *(float2*)&cp[(d + 8) * DHEAD + col] = make_float2(acc[ni][2], acc[ni][3]);
    }
}

// ---------------------------------------------------------------------------
// Reduce chunks + divide by ksum, emit ctxh fp16 transposed [bh][e][d]
// ---------------------------------------------------------------------------
__global__ void ctx_reduce_kernel(const float* __restrict__ ctxp,
                                  const float* __restrict__ ksum,
                                  __half* __restrict__ ctxh, int b_base) {
    int i = b_base * HEADS * DHEAD * DHEAD + blockIdx.x * 256 + threadIdx.x;
    int bh = i >> 12;
    int rem = i & 4095;
    int d = rem >> 6, e = rem & 63;
    float s = 0.f;
#pragma unroll
    for (int c = 0; c < NCHUNK; c++)
        s += ctxp[(size_t)c * (BH * DHEAD * DHEAD) + i];
    int b = bh >> 3, h = bh & 7;
    float kv = ksum[(size_t)b * HIDDEN + h * DHEAD + d];
    ctxh[((size_t)bh << 12) + e * DHEAD + d] = __float2half(s / kv);
}

// ---------------------------------------------------------------------------
// Mega out-kernel: phase 0 attn B-tile in smem, phase 1 out-GEMM + epilogue.
// ---------------------------------------------------------------------------
#define EQ_LD 72
#define EQ_BYTES (8 * 64 * EQ_LD * 2)
#define REGION0 (2 * EQ_BYTES)
#define OA_BYTES (512 * H_LD * 2)
#define BS_LD 520
#define BS_BYTES (64 * BS_LD * 2)
#define OUT_SMEM (REGION0 + BS_BYTES)

__global__ __launch_bounds__(512) void gemm_out_mega(
    const __half* __restrict__ wouth, const __half* __restrict__ expqT,
    const float* __restrict__ qsum, const __half* __restrict__ ctxh,
    const float* __restrict__ bias, const float* __restrict__ gout,
    const float* __restrict__ x, float* __restrict__ out, int b_base) {
    __shared__ float colsum[64];
    __shared__ float qs_s[8][64];
    uint32_t sbase = (uint32_t)__cvta_generic_to_shared(sgm_h);
    uint32_t eq = sbase;
    uint32_t ch = sbase + EQ_BYTES;
    uint32_t bs = sbase + REGION0;

    const int tid = threadIdx.x;
    const int lane = tid & 31;
    const int warp = tid >> 5;
    const int gid = lane >> 2;
    const int t4 = lane & 3;
    const int t8 = lane >> 3;
    const int r8 = lane & 7;
    const int bz = blockIdx.y + b_base;
    const int l0 = blockIdx.x * 64;

#pragma unroll
    for (int i = 0; i < 8; i++) {
        int flat = i * 512 + tid;
        int h = flat >> 9, row = (flat >> 3) & 63, seg = flat & 7;
        const __half* qp = expqT + (((size_t)bz * HEADS + h) * L + l0 + row) * DHEAD;
        cp_async16(eq + (h * 64 * EQ_LD + row * EQ_LD + seg * 8) * 2, qp + seg * 8);
        const __half* cpp = ctxh + (((size_t)bz * HEADS + h) << 12) + (size_t)row * DHEAD;
        cp_async16(ch + (h * 64 * EQ_LD + row * EQ_LD + seg * 8) * 2, cpp + seg * 8);
    }
    if (tid < 128) {
        int h = tid >> 4, seg = tid & 15;
        const float* qp = qsum + ((size_t)bz * HEADS + h) * L + l0 + seg * 4;
        cp_async16((uint32_t)__cvta_generic_to_shared(&qs_s[h][seg * 4]), qp);
    }
    cp_commit();
    cp_wait<0>();
    __syncthreads();

    {
        const int h = warp >> 1;
        const int sub = warp & 1;
        uint32_t eqh = eq + (h * 64 * EQ_LD) * 2;
        uint32_t chh = ch + (h * 64 * EQ_LD) * 2;
        float pacc[2][8][4];
#pragma unroll
        for (int mi = 0; mi < 2; mi++)
#pragma unroll
            for (int ni = 0; ni < 8; ni++)
#pragma unroll
                for (int r = 0; r < 4; r++) pacc[mi][ni][r] = 0.f;

#pragma unroll
        for (int kt = 0; kt < 4; kt++) {
            const int kbh = kt * 16;
            uint32_t af[2][4], bf[8][2];
#pragma unroll
            for (int mi = 0; mi < 2; mi++) {
                int row = sub * 32 + mi * 16 + r8 + (t8 & 1) * 8;
                int col = kbh + (t8 >> 1) * 8;
                ldsm_x4(af[mi], eqh + (row * EQ_LD + col) * 2);
            }
#pragma unroll
            for (int np = 0; np < 4; np++) {
                int row = np * 16 + r8 + (t8 >> 1) * 8;
                int col = kbh + (t8 & 1) * 8;
                uint32_t r4[4];
                ldsm_x4(r4, chh + (row * EQ_LD + col) * 2);
                bf[np * 2][0] = r4[0]; bf[np * 2][1] = r4[1];
                bf[np * 2 + 1][0] = r4[2]; bf[np * 2 + 1][1] = r4[3];
            }
#pragma unroll
            for (int mi = 0; mi < 2; mi++)
#pragma unroll
                for (int ni = 0; ni < 8; ni++)
                    mma_f16(pacc[mi][ni], af[mi], bf[ni]);
        }
#pragma unroll
        for (int mi = 0; mi < 2; mi++) {
            int r0 = sub * 32 + mi * 16 + gid;
            float inv0 = ATTN_SCALE / qs_s[h][r0];
            float inv1 = ATTN_SCALE / qs_s[h][r0 + 8];
#pragma unroll
            for (int ni = 0; ni < 8; ni++) {
                int col = h * 64 + ni * 8 + t4 * 2;
                __half* b0 = (__half*)sgm_h + REGION0 / 2 + r0 * BS_LD + col;
                __half* b1 = (__half*)sgm_h + REGION0 / 2 + (r0 + 8) * BS_LD + col;
                *(__half2*)b0 = __floats2half2_rn(pacc[mi][ni][0] * inv0,
                                                  pacc[mi][ni][1] * inv0);
                *(__half2*)b1 = __floats2half2_rn(pacc[mi][ni][2] * inv1,
                                                  pacc[mi][ni][3] * inv1);
            }
        }
    }
    __syncthreads();

    float acc[2][8][4];
#pragma unroll
    for (int mi = 0; mi < 2; mi++)
#pragma unroll
        for (int ni = 0; ni < 8; ni++)
#pragma unroll
            for (int r = 0; r < 4; r++) acc[mi][ni][r] = 0.f;

    auto load_stage = [&](int kt) {
        uint32_t sA = sbase + (kt % 3) * OA_BYTES;
        int k0 = kt * 32;
#pragma unroll
        for (int i = 0; i < 4; i++) {
            int c = tid + i * 512;
            int row = c >> 2, kc = (c & 3) * 8;
            cp_async16(sA + (row * H_LD + kc) * 2,
                       wouth + (size_t)row * HIDDEN + k0 + kc);
        }
    };

    const int ktiles = HIDDEN >> 5;
#pragma unroll
    for (int s = 0; s < 2; s++) {
        load_stage(s);
        cp_commit();
    }
    cp_wait<1>();
    __syncthreads();

    for (int kt = 0; kt < ktiles; kt++) {
        uint32_t abase = sbase + (kt % 3) * OA_BYTES;
#pragma unroll
        for (int kk = 0; kk < 2; kk++) {
            const int kbh = kk * 16;
            uint32_t af[2][4], bf[8][2];
#pragma unroll
            for (int mi = 0; mi < 2; mi++) {
                int row = warp * 32 + mi * 16 + r8 + (t8 & 1) * 8;
                int col = kbh + (t8 >> 1) * 8;
                ldsm_x4(af[mi], abase + (row * H_LD + col) * 2);
            }
#pragma unroll
            for (int np = 0; np < 4; np++) {
                int row = np * 16 + r8 + (t8 >> 1) * 8;
                int col = kt * 32 + kbh + (t8 & 1) * 8;
                uint32_t r4[4];
                ldsm_x4(r4, bs + (row * BS_LD + col) * 2);
                bf[np * 2][0] = r4[0]; bf[np * 2][1] = r4[1];
                bf[np * 2 + 1][0] = r4[2]; bf[np * 2 + 1][1] = r4[3];
            }
#pragma unroll
            for (int mi = 0; mi < 2; mi++)
#pragma unroll
                for (int ni = 0; ni < 8; ni++)
                    mma_f16(acc[mi][ni], af[mi], bf[ni]);
        }
        int nt = kt + 2;
        if (nt < ktiles) {
            load_stage(nt);
            cp_commit();
            cp_wait<1>();
        } else {
            cp_wait<0>();
        }
        __syncthreads();
    }

    float bvs[2][2];
#pragma unroll
    for (int mi = 0; mi < 2; mi++) {
        int r0 = warp * 32 + mi * 16 + gid;
        bvs[mi][0] = bias[r0];
        bvs[mi][1] = bias[r0 + 8];
    }
    if (tid < 64) colsum[tid] = 0.f;
    __syncthreads();

#pragma unroll
    for (int ni = 0; ni < 8; ni++) {
#pragma unroll
        for (int c01 = 0; c01 < 2; c01++) {
            float part = 0.f;
#pragma unroll
            for (int mi = 0; mi < 2; mi++) {
                float v0 = acc[mi][ni][c01] + bvs[mi][0];
                float v1 = acc[mi][ni][2 + c01] + bvs[mi][1];
                acc[mi][ni][c01] = v0;
                acc[mi][ni][2 + c01] = v1;
                part += v0 * v0 + v1 * v1;
            }
            part += __shfl_xor_sync(0xFFFFFFFFu, part, 4);
            part += __shfl_xor_sync(0xFFFFFFFFu, part, 8);
            part += __shfl_xor_sync(0xFFFFFFFFu, part, 16);
            if (gid == 0) atomicAdd(&colsum[ni * 8 + t4 * 2 + c01], part);
        }
    }
    __syncthreads();

    float scl[8][2];
#pragma unroll
    for (int ni = 0; ni < 8; ni++) {
        int col = ni * 8 + t4 * 2;
        scl[ni][0] = SQRT_C / fmaxf(sqrtf(colsum[col]), 1e-12f);
        scl[ni][1] = SQRT_C / fmaxf(sqrtf(colsum[col + 1]), 1e-12f);
    }

#pragma unroll
    for (int mi = 0; mi < 2; mi++) {
        int r0 = warp * 32 + mi * 16 + gid;
        float g0 = gout[r0], g1 = gout[r0 + 8];
        const float* xr0 = x + ((size_t)bz * C + r0) * L + l0;
        const float* xr1 = x + ((size_t)bz * C + r0 + 8) * L + l0;
        float* or0 = out + ((size_t)bz * C + r0) * L + l0;
        float* or1 = out + ((size_t)bz * C + r0 + 8) * L + l0;
#pragma unroll
        for (int ni = 0; ni < 8; ni++) {
            int col = ni * 8 + t4 * 2;
            float2 xv0 = *(const float2*)&xr0[col];
            float2 xv1 = *(const float2*)&xr1[col];
            float2 v0 = make_float2(acc[mi][ni][0] * scl[ni][0] * g0 + xv0.x,
                                    acc[mi][ni][1] * scl[ni][1] * g0 + xv0.y);
            float2 v1 = make_float2(acc[mi][ni][2] * scl[ni][0] * g1 + xv1.x,
                                    acc[mi][ni][3] * scl[ni][1] * g1 + xv1.y);
            *(float2*)&or0[col] = v0;
            *(float2*)&or1[col] = v1;
        }
    }
}

// ---------------------------------------------------------------------------
extern "C" void kernel_launch(void* const* d_in, const int* in_sizes, int n_in,
                              void* d_out, int out_size) {
    const float* x     = (const float*)d_in[0];
    const float* g_in  = (const float*)d_in[1];
    const float* w_qkv = (const float*)d_in[2];
    const float* w_out = (const float*)d_in[3];
    const float* b_out = (const float*)d_in[4];
    const float* g_out = (const float*)d_in[5];
    float* out = (float*)d_out;

    __half *w2h, *wouth, *xhT, *qkvh, *expqT, *ctxh;
    float *qsum, *ksum, *ctxp;
    cudaGetSymbolAddress((void**)&w2h, g_w2h);
    cudaGetSymbolAddress((void**)&wouth, g_wouth);
    cudaGetSymbolAddress((void**)&xhT, g_xhT);
    cudaGetSymbolAddress((void**)&qkvh, g_qkvh);
    cudaGetSymbolAddress((void**)&expqT, g_expqT);
    cudaGetSymbolAddress((void**)&qsum, g_qsum);
    cudaGetSymbolAddress((void**)&ksum, g_ksum);
    cudaGetSymbolAddress((void**)&ctxp, g_ctxp);
    cudaGetSymbolAddress((void**)&ctxh, g_ctxh);

    cudaFuncSetAttribute(gemm_qkv, cudaFuncAttributeMaxDynamicSharedMemorySize,
                         GEMM_SMEM);
    cudaFuncSetAttribute(gemm_out_mega, cudaFuncAttributeMaxDynamicSharedMemorySize,
                         OUT_SMEM);

    // Fork/join two-stream batch pipeline (capture-safe event pattern).
    cudaStream_t s2;
    cudaStreamCreateWithFlags(&s2, cudaStreamNonBlocking);
    cudaEvent_t eRoot, ePro, eDone;
    cudaEventCreateWithFlags(&eRoot, cudaEventDisableTiming);
    cudaEventCreateWithFlags(&ePro, cudaEventDisableTiming);
    cudaEventCreateWithFlags(&eDone, cudaEventDisableTiming);

    cudaEventRecord(eRoot, 0);
    cudaStreamWaitEvent(s2, eRoot, 0);

    prologue_kernel<<<(QKV_CH * C) / 256, 256>>>(w_qkv, g_in, w_out,
                                                 w2h, wouth, ksum);
    cudaEventRecord(ePro, 0);

    normxpose_kernel<<<dim3(L / 32, BHALF), 256, 0, s2>>>(x, xhT, BHALF);
    cudaStreamWaitEvent(s2, ePro, 0);

    normxpose_kernel<<<dim3(L / 32, BHALF), 256>>>(x, xhT, 0);

    gemm_qkv<<<dim3(L / 128, QKV_CH / 128, BHALF), 256, GEMM_SMEM>>>(
        w2h, xhT, qkvh, expqT, qsum, ksum, C, L,
        (size_t)L * C, (size_t)QKV_CH * L, 0);
    gemm_qkv<<<dim3(L / 128, QKV_CH / 128, BHALF), 256, GEMM_SMEM, s2>>>(
        w2h, xhT, qkvh, expqT, qsum, ksum, C, L,
        (size_t)L * C, (size_t)QKV_CH * L, BHALF);

    ctx_part_mma<<<dim3(BHALF * HEADS, NCHUNK), 128>>>(qkvh, ctxp, 0);
    ctx_part_mma<<<dim3(BHALF * HEADS, NCHUNK), 128, 0, s2>>>(qkvh, ctxp, BHALF);

    ctx_reduce_kernel<<<(BHALF * HEADS * DHEAD * DHEAD) / 256, 256>>>(
        ctxp, ksum, ctxh, 0);
    ctx_reduce_kernel<<<(BHALF * HEADS * DHEAD * DHEAD) / 256, 256, 0, s2>>>(
        ctxp, ksum, ctxh, BHALF);

    gemm_out_mega<<<dim3(L / 64, BHALF), 512, OUT_SMEM>>>(
        wouth, expqT, qsum, ctxh, b_out, g_out, x, out, 0);
    gemm_out_mega<<<dim3(L / 64, BHALF), 512, OUT_SMEM, s2>>>(
        wouth, expqT, qsum, ctxh, b_out, g_out, x, out, BHALF);

    cudaEventRecord(eDone, s2);
    cudaStreamWaitEvent(0, eDone, 0);
    // Streams/events intentionally not destroyed (capture-safe; O(1) calls).
}